// round 4
// baseline (speedup 1.0000x reference)
#include <cuda_runtime.h>
#include <math.h>
#include <math_constants.h>

#define B_   32
#define V_   2048
#define K_   40
#define KP1  41
#define FIN  64
#define D_   4
#define P_   64
#define FILT 128
#define N_   (B_ * V_)
#define QPB  8

// ---- scratch (static device arrays: no allocation allowed) ----
__device__ float g_coords[N_ * 4];                  // 1 MB
__device__ float g_feats[(size_t)N_ * FIN];         // 16 MB
__device__ float g_coll[(size_t)N_ * 2 * P_];       // 32 MB

// ============================================================
// Kernel 1: coords = x@W_s + b_s ; feats = x@W_f + b_f
// block (64,4): 4 rows per block, one output column per thread
// ============================================================
__global__ void __launch_bounds__(256) k_transform(
    const float* __restrict__ x,
    const float* __restrict__ Ws, const float* __restrict__ bs,
    const float* __restrict__ Wf, const float* __restrict__ bf)
{
    __shared__ float xs[4][FIN];
    int row = blockIdx.x * 4 + threadIdx.y;
    int c = threadIdx.x;
    xs[threadIdx.y][c] = x[(size_t)row * FIN + c];
    __syncthreads();

    float acc = 0.f;
    #pragma unroll
    for (int k = 0; k < FIN; k++)
        acc = fmaf(xs[threadIdx.y][k], Wf[k * P_ + c], acc);
    g_feats[(size_t)row * FIN + c] = acc + bf[c];

    if (c < D_) {
        float a2 = 0.f;
        #pragma unroll
        for (int k = 0; k < FIN; k++)
            a2 = fmaf(xs[threadIdx.y][k], Ws[k * D_ + c], a2);
        g_coords[row * 4 + c] = a2 + bs[c];
    }
}

// ============================================================
// Kernel 2: exact KNN (top-41 smallest d2 with lax.top_k tie-break,
// drop global min) + Gaussian-weighted feature max/mean pooling.
// One warp per query. d2 keys kept in registers (64/lane).
// ============================================================
__device__ __forceinline__ unsigned keyof(float d2) {
    unsigned u = __float_as_uint(d2);
    // monotonic float->uint map (handles potential tiny negative d2)
    u ^= (u & 0x80000000u) ? 0xFFFFFFFFu : 0x80000000u;
    return u;
}

__device__ __forceinline__ unsigned long long ullmin_(unsigned long long a, unsigned long long b) {
    return a < b ? a : b;
}

__global__ void __launch_bounds__(256, 2) k_knn()
{
    __shared__ float4 sc[V_];               // 32 KB: batch coords
    __shared__ float  ssq[V_];              // 8 KB : squared norms
    __shared__ int    s_idx[QPB][KP1 + 7];
    __shared__ float  s_w[QPB][KP1 + 7];
    __shared__ int    s_cnt[QPB];

    const int b   = blockIdx.y;
    const int tid = threadIdx.x;
    const float4* cg = reinterpret_cast<const float4*>(g_coords) + (size_t)b * V_;
    for (int t = tid; t < V_; t += 256) {
        float4 c = cg[t];
        sc[t]  = c;
        float s = c.x * c.x;
        s = fmaf(c.y, c.y, s); s = fmaf(c.z, c.z, s); s = fmaf(c.w, c.w, s);
        ssq[t] = s;
    }
    __syncthreads();

    const int w    = tid >> 5;
    const int lane = tid & 31;
    const int q    = blockIdx.x * QPB + w;

    const float4 qc  = sc[q];
    const float  qsq = ssq[q];

    // ---- distance keys (same sq+sq-2*dot form as reference selection) ----
    unsigned key[64];
    #pragma unroll
    for (int j = 0; j < 64; j++) {
        int idx = j * 32 + lane;
        float4 c = sc[idx];
        float dot = qc.x * c.x;
        dot = fmaf(qc.y, c.y, dot);
        dot = fmaf(qc.z, c.z, dot);
        dot = fmaf(qc.w, c.w, dot);
        float d2 = qsq + ssq[idx] - 2.f * dot;
        key[j] = keyof(d2);
    }

    // ---- per-lane two smallest -> tight binary-search bounds ----
    unsigned m1 = 0xFFFFFFFFu, m2 = 0xFFFFFFFFu;
    #pragma unroll
    for (int j = 0; j < 64; j++) {
        unsigned u = key[j];
        unsigned nm1 = min(m1, u);
        unsigned nm2 = min(m2, max(m1, u));
        m1 = nm1; m2 = nm2;
    }
    unsigned lo = m1, hi = m2;
    #pragma unroll
    for (int o = 16; o; o >>= 1) {
        lo = min(lo, __shfl_xor_sync(0xffffffffu, lo, o));
        hi = max(hi, __shfl_xor_sync(0xffffffffu, hi, o));
    }
    // invariant: cnt(<=lo-1) < 41  (lo = global min),  cnt(<=hi) >= 64 >= 41

    // ---- binary search smallest T with cnt(<=T) >= 41 ----
    unsigned T = 0;
    bool found = false;
    while (lo < hi) {
        unsigned mid = lo + ((hi - lo) >> 1);
        int c = 0;
        #pragma unroll
        for (int j = 0; j < 64; j++) c += (key[j] <= mid) ? 1 : 0;
        #pragma unroll
        for (int o = 16; o; o >>= 1) c += __shfl_xor_sync(0xffffffffu, c, o);
        if (c == KP1) {   // exact: T = max selected key
            unsigned mx = 0;
            #pragma unroll
            for (int j = 0; j < 64; j++) if (key[j] <= mid) mx = max(mx, key[j]);
            #pragma unroll
            for (int o = 16; o; o >>= 1) mx = max(mx, __shfl_xor_sync(0xffffffffu, mx, o));
            T = mx; found = true; break;
        }
        if (c > KP1) hi = mid; else lo = mid + 1;
    }
    if (!found) T = lo;

    // ---- selection flags: all key<T, plus smallest-index elements with key==T ----
    int c_less = 0;
    #pragma unroll
    for (int j = 0; j < 64; j++) c_less += (key[j] < T) ? 1 : 0;
    #pragma unroll
    for (int o = 16; o; o >>= 1) c_less += __shfl_xor_sync(0xffffffffu, c_less, o);
    const int take_eq = KP1 - c_less;

    unsigned long long selmask = 0ull;
    unsigned long long mymin = 0xFFFFFFFFFFFFFFFFull;
    int running = 0;
    const unsigned lanemask_lt = (1u << lane) - 1u;
    #pragma unroll
    for (int j = 0; j < 64; j++) {
        bool eq = (key[j] == T);
        unsigned bal = __ballot_sync(0xffffffffu, eq);
        bool sel = (key[j] < T);
        if (eq) {
            int rank = running + __popc(bal & lanemask_lt);
            sel = sel || (rank < take_eq);
        }
        running += __popc(bal);
        if (sel) {
            selmask |= (1ull << j);
            unsigned long long ck =
                ((unsigned long long)key[j] << 32) | (unsigned)(j * 32 + lane);
            mymin = ullmin_(mymin, ck);
        }
    }
    #pragma unroll
    for (int o = 16; o; o >>= 1)
        mymin = ullmin_(mymin, __shfl_xor_sync(0xffffffffu, mymin, o));
    const int dropidx = (int)(unsigned)(mymin & 0xffffffffull);  // min (key,idx): dropped

    // ---- build neighbor list (order irrelevant for max/mean) ----
    if (lane == 0) s_cnt[w] = 0;
    __syncwarp();
    unsigned long long m = selmask;
    while (m) {
        int j = __ffsll((long long)m) - 1;
        m &= m - 1;
        int idx = j * 32 + lane;
        if (idx != dropidx) {
            int p = atomicAdd(&s_cnt[w], 1);
            float4 c = sc[idx];
            float dx = qc.x - c.x, dy = qc.y - c.y, dz = qc.z - c.z, dw = qc.w - c.w;
            float dist = dx * dx;
            dist = fmaf(dy, dy, dist);
            dist = fmaf(dz, dz, dist);
            dist = fmaf(dw, dw, dist);
            s_idx[w][p] = idx;
            s_w[w][p]   = expf(-fabsf(dist * 10.f));  // reference weight form
        }
    }
    __syncwarp();
    const int cnt = s_cnt[w];   // == 40 by construction

    // ---- weighted max / mean pooling over neighbors ----
    const float* fb = g_feats + (size_t)b * V_ * FIN;
    float mx0 = -CUDART_INF_F, mx1 = -CUDART_INF_F, sm0 = 0.f, sm1 = 0.f;
    for (int n = 0; n < cnt; n++) {
        int   idx = s_idx[w][n];
        float wt  = s_w[w][n];
        float f0 = fb[(size_t)idx * FIN + lane];
        float f1 = fb[(size_t)idx * FIN + 32 + lane];
        float v0 = f0 * wt, v1 = f1 * wt;
        mx0 = fmaxf(mx0, v0); mx1 = fmaxf(mx1, v1);
        sm0 += v0;            sm1 += v1;
    }
    const int grow = b * V_ + q;
    float* o = g_coll + (size_t)grow * (2 * P_);
    o[lane]       = mx0;
    o[32 + lane]  = mx1;
    o[64 + lane]  = sm0 * (1.f / (float)K_);
    o[96 + lane]  = sm1 * (1.f / (float)K_);
}

// ============================================================
// Kernel 3: out = tanh([x | collected] @ W_out + b_out)
// 128x128 block tile, 8x8 per thread, BK=16, K=192
// ============================================================
__global__ void __launch_bounds__(256) k_out(
    const float* __restrict__ x,
    const float* __restrict__ Wout, const float* __restrict__ bout,
    float* __restrict__ out)
{
    __shared__ float As[16 * 132];   // [k][row], padded stride
    __shared__ float Bs[16 * 128];   // [k][n]

    const int tidx = threadIdx.x;
    const int tx = tidx & 15, ty = tidx >> 4;
    const int r0 = blockIdx.x * 128;

    float acc[8][8];
    #pragma unroll
    for (int i = 0; i < 8; i++)
        #pragma unroll
        for (int j = 0; j < 8; j++) acc[i][j] = 0.f;

    for (int kt = 0; kt < 12; kt++) {
        // load A tile (U = [x | collected])
        #pragma unroll
        for (int i = 0; i < 2; i++) {
            int t   = tidx + i * 256;       // 0..511
            int row = t >> 2;               // 0..127
            int kq  = (t & 3) * 4;          // 0,4,8,12
            int gk  = kt * 16 + kq;
            const float* src = (gk < FIN)
                ? (x      + (size_t)(r0 + row) * FIN  + gk)
                : (g_coll + (size_t)(r0 + row) * 128 + (gk - FIN));
            float4 v = *reinterpret_cast<const float4*>(src);
            As[(kq + 0) * 132 + row] = v.x;
            As[(kq + 1) * 132 + row] = v.y;
            As[(kq + 2) * 132 + row] = v.z;
            As[(kq + 3) * 132 + row] = v.w;
        }
        // load B tile (W_out rows kt*16 .. kt*16+15)
        #pragma unroll
        for (int i = 0; i < 2; i++) {
            int t  = tidx + i * 256;
            int kr = t >> 5;                // 0..15
            int n  = (t & 31) * 4;          // 0..124
            *reinterpret_cast<float4*>(&Bs[kr * 128 + n]) =
                *reinterpret_cast<const float4*>(Wout + (size_t)(kt * 16 + kr) * 128 + n);
        }
        __syncthreads();

        #pragma unroll
        for (int k = 0; k < 16; k++) {
            float a[8], bb[8];
            *reinterpret_cast<float4*>(&a[0]) =
                *reinterpret_cast<const float4*>(&As[k * 132 + ty * 8]);
            *reinterpret_cast<float4*>(&a[4]) =
                *reinterpret_cast<const float4*>(&As[k * 132 + ty * 8 + 4]);
            *reinterpret_cast<float4*>(&bb[0]) =
                *reinterpret_cast<const float4*>(&Bs[k * 128 + tx * 8]);
            *reinterpret_cast<float4*>(&bb[4]) =
                *reinterpret_cast<const float4*>(&Bs[k * 128 + tx * 8 + 4]);
            #pragma unroll
            for (int i = 0; i < 8; i++)
                #pragma unroll
                for (int j = 0; j < 8; j++)
                    acc[i][j] = fmaf(a[i], bb[j], acc[i][j]);
        }
        __syncthreads();
    }

    float bias[8];
    *reinterpret_cast<float4*>(&bias[0]) = *reinterpret_cast<const float4*>(&bout[tx * 8]);
    *reinterpret_cast<float4*>(&bias[4]) = *reinterpret_cast<const float4*>(&bout[tx * 8 + 4]);

    #pragma unroll
    for (int i = 0; i < 8; i++) {
        int row = r0 + ty * 8 + i;
        float4 o0, o1;
        o0.x = tanhf(acc[i][0] + bias[0]);
        o0.y = tanhf(acc[i][1] + bias[1]);
        o0.z = tanhf(acc[i][2] + bias[2]);
        o0.w = tanhf(acc[i][3] + bias[3]);
        o1.x = tanhf(acc[i][4] + bias[4]);
        o1.y = tanhf(acc[i][5] + bias[5]);
        o1.z = tanhf(acc[i][6] + bias[6]);
        o1.w = tanhf(acc[i][7] + bias[7]);
        *reinterpret_cast<float4*>(&out[(size_t)row * 128 + tx * 8])     = o0;
        *reinterpret_cast<float4*>(&out[(size_t)row * 128 + tx * 8 + 4]) = o1;
    }
}

// ============================================================
extern "C" void kernel_launch(void* const* d_in, const int* in_sizes, int n_in,
                              void* d_out, int out_size)
{
    const float* x    = (const float*)d_in[0];
    // d_in[1] = row_splits (uniform; reference ignores it via reshape)
    const float* Ws   = (const float*)d_in[2];
    const float* bs   = (const float*)d_in[3];
    const float* Wf   = (const float*)d_in[4];
    const float* bf   = (const float*)d_in[5];
    const float* Wout = (const float*)d_in[6];
    const float* bout = (const float*)d_in[7];
    float* out = (float*)d_out;

    k_transform<<<N_ / 4, dim3(64, 4)>>>(x, Ws, bs, Wf, bf);
    k_knn<<<dim3(V_ / QPB, B_), 256>>>();
    k_out<<<N_ / 128, 256>>>(x, Wout, bout, out);
}

// round 5
// speedup vs baseline: 1.0537x; 1.0537x over previous
#include <cuda_runtime.h>
#include <math.h>
#include <math_constants.h>

#define B_   32
#define V_   2048
#define K_   40
#define KP1  41
#define FIN  64
#define D_   4
#define P_   64
#define FILT 128
#define N_   (B_ * V_)
#define QPB  8

// ---- scratch (static device arrays: no allocation allowed) ----
__device__ float g_coords[N_ * 4];                  // 1 MB
__device__ float g_feats[(size_t)N_ * FIN];         // 16 MB
__device__ float g_coll[(size_t)N_ * 2 * P_];       // 32 MB

// ============================================================
// Kernel 1: coords = x@W_s + b_s ; feats = x@W_f + b_f
// block (64,4): 4 rows per block, one output column per thread
// ============================================================
__global__ void __launch_bounds__(256) k_transform(
    const float* __restrict__ x,
    const float* __restrict__ Ws, const float* __restrict__ bs,
    const float* __restrict__ Wf, const float* __restrict__ bf)
{
    __shared__ float xs[4][FIN];
    int row = blockIdx.x * 4 + threadIdx.y;
    int c = threadIdx.x;
    xs[threadIdx.y][c] = x[(size_t)row * FIN + c];
    __syncthreads();

    float acc = 0.f;
    #pragma unroll
    for (int k = 0; k < FIN; k++)
        acc = fmaf(xs[threadIdx.y][k], Wf[k * P_ + c], acc);
    g_feats[(size_t)row * FIN + c] = acc + bf[c];

    if (c < D_) {
        float a2 = 0.f;
        #pragma unroll
        for (int k = 0; k < FIN; k++)
            a2 = fmaf(xs[threadIdx.y][k], Ws[k * D_ + c], a2);
        g_coords[row * 4 + c] = a2 + bs[c];
    }
}

// ============================================================
// Kernel 2: exact KNN (top-41 smallest d2 with lax.top_k tie-break,
// drop global min) + Gaussian-weighted feature max/mean pooling.
// One warp per query. d2 keys kept in registers (64/lane).
// ============================================================
__device__ __forceinline__ unsigned keyof(float d2) {
    unsigned u = __float_as_uint(d2);
    // monotonic float->uint map (handles potential tiny negative d2)
    u ^= (u & 0x80000000u) ? 0xFFFFFFFFu : 0x80000000u;
    return u;
}

__device__ __forceinline__ unsigned long long ullmin_(unsigned long long a, unsigned long long b) {
    return a < b ? a : b;
}

__global__ void __launch_bounds__(256, 2) k_knn()
{
    __shared__ float4 sc[V_];               // 32 KB: batch coords
    __shared__ float  ssq[V_];              // 8 KB : squared norms
    __shared__ int    s_idx[QPB][KP1 + 7];
    __shared__ float  s_w[QPB][KP1 + 7];
    __shared__ int    s_cnt[QPB];

    const int b   = blockIdx.y;
    const int tid = threadIdx.x;
    const float4* cg = reinterpret_cast<const float4*>(g_coords) + (size_t)b * V_;
    for (int t = tid; t < V_; t += 256) {
        float4 c = cg[t];
        sc[t]  = c;
        float s = c.x * c.x;
        s = fmaf(c.y, c.y, s); s = fmaf(c.z, c.z, s); s = fmaf(c.w, c.w, s);
        ssq[t] = s;
    }
    __syncthreads();

    const int w    = tid >> 5;
    const int lane = tid & 31;
    const int q    = blockIdx.x * QPB + w;

    const float4 qc  = sc[q];
    const float  qsq = ssq[q];

    // ---- distance keys (same sq+sq-2*dot form as reference selection) ----
    unsigned key[64];
    #pragma unroll
    for (int j = 0; j < 64; j++) {
        int idx = j * 32 + lane;
        float4 c = sc[idx];
        float dot = qc.x * c.x;
        dot = fmaf(qc.y, c.y, dot);
        dot = fmaf(qc.z, c.z, dot);
        dot = fmaf(qc.w, c.w, dot);
        float d2 = qsq + ssq[idx] - 2.f * dot;
        key[j] = keyof(d2);
    }

    // ---- per-lane two smallest -> tight binary-search bounds ----
    unsigned m1 = 0xFFFFFFFFu, m2 = 0xFFFFFFFFu;
    #pragma unroll
    for (int j = 0; j < 64; j++) {
        unsigned u = key[j];
        unsigned nm1 = min(m1, u);
        unsigned nm2 = min(m2, max(m1, u));
        m1 = nm1; m2 = nm2;
    }
    unsigned lo = m1, hi = m2;
    #pragma unroll
    for (int o = 16; o; o >>= 1) {
        lo = min(lo, __shfl_xor_sync(0xffffffffu, lo, o));
        hi = max(hi, __shfl_xor_sync(0xffffffffu, hi, o));
    }
    // invariant: cnt(<=lo-1) < 41  (lo = global min),  cnt(<=hi) >= 64 >= 41

    // ---- binary search smallest T with cnt(<=T) >= 41 ----
    unsigned T = 0;
    bool found = false;
    while (lo < hi) {
        unsigned mid = lo + ((hi - lo) >> 1);
        int c = 0;
        #pragma unroll
        for (int j = 0; j < 64; j++) c += (key[j] <= mid) ? 1 : 0;
        #pragma unroll
        for (int o = 16; o; o >>= 1) c += __shfl_xor_sync(0xffffffffu, c, o);
        if (c == KP1) {   // exact: T = max selected key
            unsigned mx = 0;
            #pragma unroll
            for (int j = 0; j < 64; j++) if (key[j] <= mid) mx = max(mx, key[j]);
            #pragma unroll
            for (int o = 16; o; o >>= 1) mx = max(mx, __shfl_xor_sync(0xffffffffu, mx, o));
            T = mx; found = true; break;
        }
        if (c > KP1) hi = mid; else lo = mid + 1;
    }
    if (!found) T = lo;

    // ---- selection flags: all key<T, plus smallest-index elements with key==T ----
    int c_less = 0;
    #pragma unroll
    for (int j = 0; j < 64; j++) c_less += (key[j] < T) ? 1 : 0;
    #pragma unroll
    for (int o = 16; o; o >>= 1) c_less += __shfl_xor_sync(0xffffffffu, c_less, o);
    const int take_eq = KP1 - c_less;

    unsigned long long selmask = 0ull;
    unsigned long long mymin = 0xFFFFFFFFFFFFFFFFull;
    int running = 0;
    const unsigned lanemask_lt = (1u << lane) - 1u;
    #pragma unroll
    for (int j = 0; j < 64; j++) {
        bool eq = (key[j] == T);
        unsigned bal = __ballot_sync(0xffffffffu, eq);
        bool sel = (key[j] < T);
        if (eq) {
            int rank = running + __popc(bal & lanemask_lt);
            sel = sel || (rank < take_eq);
        }
        running += __popc(bal);
        if (sel) {
            selmask |= (1ull << j);
            unsigned long long ck =
                ((unsigned long long)key[j] << 32) | (unsigned)(j * 32 + lane);
            mymin = ullmin_(mymin, ck);
        }
    }
    #pragma unroll
    for (int o = 16; o; o >>= 1)
        mymin = ullmin_(mymin, __shfl_xor_sync(0xffffffffu, mymin, o));
    const int dropidx = (int)(unsigned)(mymin & 0xffffffffull);  // min (key,idx): dropped

    // ---- build neighbor list (order irrelevant for max/mean) ----
    if (lane == 0) s_cnt[w] = 0;
    __syncwarp();
    unsigned long long m = selmask;
    while (m) {
        int j = __ffsll((long long)m) - 1;
        m &= m - 1;
        int idx = j * 32 + lane;
        if (idx != dropidx) {
            int p = atomicAdd(&s_cnt[w], 1);
            float4 c = sc[idx];
            float dx = qc.x - c.x, dy = qc.y - c.y, dz = qc.z - c.z, dw = qc.w - c.w;
            float dist = dx * dx;
            dist = fmaf(dy, dy, dist);
            dist = fmaf(dz, dz, dist);
            dist = fmaf(dw, dw, dist);
            s_idx[w][p] = idx;
            s_w[w][p]   = expf(-fabsf(dist * 10.f));  // reference weight form
        }
    }
    __syncwarp();
    const int cnt = s_cnt[w];   // == 40 by construction

    // ---- weighted max / mean pooling over neighbors ----
    const float* fb = g_feats + (size_t)b * V_ * FIN;
    float mx0 = -CUDART_INF_F, mx1 = -CUDART_INF_F, sm0 = 0.f, sm1 = 0.f;
    for (int n = 0; n < cnt; n++) {
        int   idx = s_idx[w][n];
        float wt  = s_w[w][n];
        float f0 = fb[(size_t)idx * FIN + lane];
        float f1 = fb[(size_t)idx * FIN + 32 + lane];
        float v0 = f0 * wt, v1 = f1 * wt;
        mx0 = fmaxf(mx0, v0); mx1 = fmaxf(mx1, v1);
        sm0 += v0;            sm1 += v1;
    }
    const int grow = b * V_ + q;
    float* o = g_coll + (size_t)grow * (2 * P_);
    o[lane]       = mx0;
    o[32 + lane]  = mx1;
    o[64 + lane]  = sm0 * (1.f / (float)K_);
    o[96 + lane]  = sm1 * (1.f / (float)K_);
}

// ============================================================
// Kernel 3: out = tanh([x | collected] @ W_out + b_out)
// 128x128 block tile, 8x8 per thread, BK=16, K=192
// ============================================================
__global__ void __launch_bounds__(256) k_out(
    const float* __restrict__ x,
    const float* __restrict__ Wout, const float* __restrict__ bout,
    float* __restrict__ out)
{
    __shared__ float As[16 * 132];   // [k][row], padded stride
    __shared__ float Bs[16 * 128];   // [k][n]

    const int tidx = threadIdx.x;
    const int tx = tidx & 15, ty = tidx >> 4;
    const int r0 = blockIdx.x * 128;

    float acc[8][8];
    #pragma unroll
    for (int i = 0; i < 8; i++)
        #pragma unroll
        for (int j = 0; j < 8; j++) acc[i][j] = 0.f;

    for (int kt = 0; kt < 12; kt++) {
        // load A tile (U = [x | collected])
        #pragma unroll
        for (int i = 0; i < 2; i++) {
            int t   = tidx + i * 256;       // 0..511
            int row = t >> 2;               // 0..127
            int kq  = (t & 3) * 4;          // 0,4,8,12
            int gk  = kt * 16 + kq;
            const float* src = (gk < FIN)
                ? (x      + (size_t)(r0 + row) * FIN  + gk)
                : (g_coll + (size_t)(r0 + row) * 128 + (gk - FIN));
            float4 v = *reinterpret_cast<const float4*>(src);
            As[(kq + 0) * 132 + row] = v.x;
            As[(kq + 1) * 132 + row] = v.y;
            As[(kq + 2) * 132 + row] = v.z;
            As[(kq + 3) * 132 + row] = v.w;
        }
        // load B tile (W_out rows kt*16 .. kt*16+15)
        #pragma unroll
        for (int i = 0; i < 2; i++) {
            int t  = tidx + i * 256;
            int kr = t >> 5;                // 0..15
            int n  = (t & 31) * 4;          // 0..124
            *reinterpret_cast<float4*>(&Bs[kr * 128 + n]) =
                *reinterpret_cast<const float4*>(Wout + (size_t)(kt * 16 + kr) * 128 + n);
        }
        __syncthreads();

        #pragma unroll
        for (int k = 0; k < 16; k++) {
            float a[8], bb[8];
            *reinterpret_cast<float4*>(&a[0]) =
                *reinterpret_cast<const float4*>(&As[k * 132 + ty * 8]);
            *reinterpret_cast<float4*>(&a[4]) =
                *reinterpret_cast<const float4*>(&As[k * 132 + ty * 8 + 4]);
            *reinterpret_cast<float4*>(&bb[0]) =
                *reinterpret_cast<const float4*>(&Bs[k * 128 + tx * 8]);
            *reinterpret_cast<float4*>(&bb[4]) =
                *reinterpret_cast<const float4*>(&Bs[k * 128 + tx * 8 + 4]);
            #pragma unroll
            for (int i = 0; i < 8; i++)
                #pragma unroll
                for (int j = 0; j < 8; j++)
                    acc[i][j] = fmaf(a[i], bb[j], acc[i][j]);
        }
        __syncthreads();
    }

    float bias[8];
    *reinterpret_cast<float4*>(&bias[0]) = *reinterpret_cast<const float4*>(&bout[tx * 8]);
    *reinterpret_cast<float4*>(&bias[4]) = *reinterpret_cast<const float4*>(&bout[tx * 8 + 4]);

    #pragma unroll
    for (int i = 0; i < 8; i++) {
        int row = r0 + ty * 8 + i;
        float4 o0, o1;
        o0.x = tanhf(acc[i][0] + bias[0]);
        o0.y = tanhf(acc[i][1] + bias[1]);
        o0.z = tanhf(acc[i][2] + bias[2]);
        o0.w = tanhf(acc[i][3] + bias[3]);
        o1.x = tanhf(acc[i][4] + bias[4]);
        o1.y = tanhf(acc[i][5] + bias[5]);
        o1.z = tanhf(acc[i][6] + bias[6]);
        o1.w = tanhf(acc[i][7] + bias[7]);
        *reinterpret_cast<float4*>(&out[(size_t)row * 128 + tx * 8])     = o0;
        *reinterpret_cast<float4*>(&out[(size_t)row * 128 + tx * 8 + 4]) = o1;
    }
}

// ============================================================
extern "C" void kernel_launch(void* const* d_in, const int* in_sizes, int n_in,
                              void* d_out, int out_size)
{
    const float* x    = (const float*)d_in[0];
    // d_in[1] = row_splits (uniform; reference ignores it via reshape)
    const float* Ws   = (const float*)d_in[2];
    const float* bs   = (const float*)d_in[3];
    const float* Wf   = (const float*)d_in[4];
    const float* bf   = (const float*)d_in[5];
    const float* Wout = (const float*)d_in[6];
    const float* bout = (const float*)d_in[7];
    float* out = (float*)d_out;

    k_transform<<<N_ / 4, dim3(64, 4)>>>(x, Ws, bs, Wf, bf);
    k_knn<<<dim3(V_ / QPB, B_), 256>>>();
    k_out<<<N_ / 128, 256>>>(x, Wout, bout, out);
}

// round 6
// speedup vs baseline: 1.0539x; 1.0002x over previous
#include <cuda_runtime.h>
#include <math.h>
#include <math_constants.h>

#define B_   32
#define V_   2048
#define K_   40
#define KP1  41
#define FIN  64
#define D_   4
#define P_   64
#define FILT 128
#define N_   (B_ * V_)
#define QPB  8

// ---- scratch (static device arrays: no allocation allowed) ----
__device__ float g_coords[N_ * 4];                  // 1 MB
__device__ float g_feats[(size_t)N_ * FIN];         // 16 MB
__device__ float g_coll[(size_t)N_ * 2 * P_];       // 32 MB

// ============================================================
// Kernel 1: coords = x@W_s + b_s ; feats = x@W_f + b_f
// block (64,4): 4 rows per block, one output column per thread
// ============================================================
__global__ void __launch_bounds__(256) k_transform(
    const float* __restrict__ x,
    const float* __restrict__ Ws, const float* __restrict__ bs,
    const float* __restrict__ Wf, const float* __restrict__ bf)
{
    __shared__ float xs[4][FIN];
    int row = blockIdx.x * 4 + threadIdx.y;
    int c = threadIdx.x;
    xs[threadIdx.y][c] = x[(size_t)row * FIN + c];
    __syncthreads();

    float acc = 0.f;
    #pragma unroll
    for (int k = 0; k < FIN; k++)
        acc = fmaf(xs[threadIdx.y][k], Wf[k * P_ + c], acc);
    g_feats[(size_t)row * FIN + c] = acc + bf[c];

    if (c < D_) {
        float a2 = 0.f;
        #pragma unroll
        for (int k = 0; k < FIN; k++)
            a2 = fmaf(xs[threadIdx.y][k], Ws[k * D_ + c], a2);
        g_coords[row * 4 + c] = a2 + bs[c];
    }
}

// ============================================================
// Kernel 2: exact KNN (top-41 smallest d2 with lax.top_k tie-break,
// drop global min) + Gaussian-weighted feature max/mean pooling.
// One warp per query. d2 keys kept in registers (64/lane).
// ============================================================
__device__ __forceinline__ unsigned keyof(float d2) {
    unsigned u = __float_as_uint(d2);
    // monotonic float->uint map (handles potential tiny negative d2)
    u ^= (u & 0x80000000u) ? 0xFFFFFFFFu : 0x80000000u;
    return u;
}

__device__ __forceinline__ unsigned long long ullmin_(unsigned long long a, unsigned long long b) {
    return a < b ? a : b;
}

__global__ void __launch_bounds__(256, 2) k_knn()
{
    __shared__ float4 sc[V_];               // 32 KB: batch coords
    __shared__ float  ssq[V_];              // 8 KB : squared norms
    __shared__ int    s_idx[QPB][KP1 + 7];
    __shared__ float  s_w[QPB][KP1 + 7];
    __shared__ int    s_cnt[QPB];

    const int b   = blockIdx.y;
    const int tid = threadIdx.x;
    const float4* cg = reinterpret_cast<const float4*>(g_coords) + (size_t)b * V_;
    for (int t = tid; t < V_; t += 256) {
        float4 c = cg[t];
        sc[t]  = c;
        float s = c.x * c.x;
        s = fmaf(c.y, c.y, s); s = fmaf(c.z, c.z, s); s = fmaf(c.w, c.w, s);
        ssq[t] = s;
    }
    __syncthreads();

    const int w    = tid >> 5;
    const int lane = tid & 31;
    const int q    = blockIdx.x * QPB + w;

    const float4 qc  = sc[q];
    const float  qsq = ssq[q];

    // ---- distance keys (same sq+sq-2*dot form as reference selection) ----
    unsigned key[64];
    #pragma unroll
    for (int j = 0; j < 64; j++) {
        int idx = j * 32 + lane;
        float4 c = sc[idx];
        float dot = qc.x * c.x;
        dot = fmaf(qc.y, c.y, dot);
        dot = fmaf(qc.z, c.z, dot);
        dot = fmaf(qc.w, c.w, dot);
        float d2 = qsq + ssq[idx] - 2.f * dot;
        key[j] = keyof(d2);
    }

    // ---- per-lane two smallest -> tight binary-search bounds ----
    unsigned m1 = 0xFFFFFFFFu, m2 = 0xFFFFFFFFu;
    #pragma unroll
    for (int j = 0; j < 64; j++) {
        unsigned u = key[j];
        unsigned nm1 = min(m1, u);
        unsigned nm2 = min(m2, max(m1, u));
        m1 = nm1; m2 = nm2;
    }
    unsigned lo = m1, hi = m2;
    #pragma unroll
    for (int o = 16; o; o >>= 1) {
        lo = min(lo, __shfl_xor_sync(0xffffffffu, lo, o));
        hi = max(hi, __shfl_xor_sync(0xffffffffu, hi, o));
    }
    // invariant: cnt(<=lo-1) < 41  (lo = global min),  cnt(<=hi) >= 64 >= 41

    // ---- binary search smallest T with cnt(<=T) >= 41 ----
    unsigned T = 0;
    bool found = false;
    while (lo < hi) {
        unsigned mid = lo + ((hi - lo) >> 1);
        int c = 0;
        #pragma unroll
        for (int j = 0; j < 64; j++) c += (key[j] <= mid) ? 1 : 0;
        #pragma unroll
        for (int o = 16; o; o >>= 1) c += __shfl_xor_sync(0xffffffffu, c, o);
        if (c == KP1) {   // exact: T = max selected key
            unsigned mx = 0;
            #pragma unroll
            for (int j = 0; j < 64; j++) if (key[j] <= mid) mx = max(mx, key[j]);
            #pragma unroll
            for (int o = 16; o; o >>= 1) mx = max(mx, __shfl_xor_sync(0xffffffffu, mx, o));
            T = mx; found = true; break;
        }
        if (c > KP1) hi = mid; else lo = mid + 1;
    }
    if (!found) T = lo;

    // ---- selection flags: all key<T, plus smallest-index elements with key==T ----
    int c_less = 0;
    #pragma unroll
    for (int j = 0; j < 64; j++) c_less += (key[j] < T) ? 1 : 0;
    #pragma unroll
    for (int o = 16; o; o >>= 1) c_less += __shfl_xor_sync(0xffffffffu, c_less, o);
    const int take_eq = KP1 - c_less;

    unsigned long long selmask = 0ull;
    unsigned long long mymin = 0xFFFFFFFFFFFFFFFFull;
    int running = 0;
    const unsigned lanemask_lt = (1u << lane) - 1u;
    #pragma unroll
    for (int j = 0; j < 64; j++) {
        bool eq = (key[j] == T);
        unsigned bal = __ballot_sync(0xffffffffu, eq);
        bool sel = (key[j] < T);
        if (eq) {
            int rank = running + __popc(bal & lanemask_lt);
            sel = sel || (rank < take_eq);
        }
        running += __popc(bal);
        if (sel) {
            selmask |= (1ull << j);
            unsigned long long ck =
                ((unsigned long long)key[j] << 32) | (unsigned)(j * 32 + lane);
            mymin = ullmin_(mymin, ck);
        }
    }
    #pragma unroll
    for (int o = 16; o; o >>= 1)
        mymin = ullmin_(mymin, __shfl_xor_sync(0xffffffffu, mymin, o));
    const int dropidx = (int)(unsigned)(mymin & 0xffffffffull);  // min (key,idx): dropped

    // ---- build neighbor list (order irrelevant for max/mean) ----
    if (lane == 0) s_cnt[w] = 0;
    __syncwarp();
    unsigned long long m = selmask;
    while (m) {
        int j = __ffsll((long long)m) - 1;
        m &= m - 1;
        int idx = j * 32 + lane;
        if (idx != dropidx) {
            int p = atomicAdd(&s_cnt[w], 1);
            float4 c = sc[idx];
            float dx = qc.x - c.x, dy = qc.y - c.y, dz = qc.z - c.z, dw = qc.w - c.w;
            float dist = dx * dx;
            dist = fmaf(dy, dy, dist);
            dist = fmaf(dz, dz, dist);
            dist = fmaf(dw, dw, dist);
            s_idx[w][p] = idx;
            s_w[w][p]   = expf(-fabsf(dist * 10.f));  // reference weight form
        }
    }
    __syncwarp();
    const int cnt = s_cnt[w];   // == 40 by construction

    // ---- weighted max / mean pooling over neighbors ----
    const float* fb = g_feats + (size_t)b * V_ * FIN;
    float mx0 = -CUDART_INF_F, mx1 = -CUDART_INF_F, sm0 = 0.f, sm1 = 0.f;
    for (int n = 0; n < cnt; n++) {
        int   idx = s_idx[w][n];
        float wt  = s_w[w][n];
        float f0 = fb[(size_t)idx * FIN + lane];
        float f1 = fb[(size_t)idx * FIN + 32 + lane];
        float v0 = f0 * wt, v1 = f1 * wt;
        mx0 = fmaxf(mx0, v0); mx1 = fmaxf(mx1, v1);
        sm0 += v0;            sm1 += v1;
    }
    const int grow = b * V_ + q;
    float* o = g_coll + (size_t)grow * (2 * P_);
    o[lane]       = mx0;
    o[32 + lane]  = mx1;
    o[64 + lane]  = sm0 * (1.f / (float)K_);
    o[96 + lane]  = sm1 * (1.f / (float)K_);
}

// ============================================================
// Kernel 3: out = tanh([x | collected] @ W_out + b_out)
// 128x128 block tile, 8x8 per thread, BK=16, K=192
// ============================================================
__global__ void __launch_bounds__(256) k_out(
    const float* __restrict__ x,
    const float* __restrict__ Wout, const float* __restrict__ bout,
    float* __restrict__ out)
{
    __shared__ float As[16 * 132];   // [k][row], padded stride
    __shared__ float Bs[16 * 128];   // [k][n]

    const int tidx = threadIdx.x;
    const int tx = tidx & 15, ty = tidx >> 4;
    const int r0 = blockIdx.x * 128;

    float acc[8][8];
    #pragma unroll
    for (int i = 0; i < 8; i++)
        #pragma unroll
        for (int j = 0; j < 8; j++) acc[i][j] = 0.f;

    for (int kt = 0; kt < 12; kt++) {
        // load A tile (U = [x | collected])
        #pragma unroll
        for (int i = 0; i < 2; i++) {
            int t   = tidx + i * 256;       // 0..511
            int row = t >> 2;               // 0..127
            int kq  = (t & 3) * 4;          // 0,4,8,12
            int gk  = kt * 16 + kq;
            const float* src = (gk < FIN)
                ? (x      + (size_t)(r0 + row) * FIN  + gk)
                : (g_coll + (size_t)(r0 + row) * 128 + (gk - FIN));
            float4 v = *reinterpret_cast<const float4*>(src);
            As[(kq + 0) * 132 + row] = v.x;
            As[(kq + 1) * 132 + row] = v.y;
            As[(kq + 2) * 132 + row] = v.z;
            As[(kq + 3) * 132 + row] = v.w;
        }
        // load B tile (W_out rows kt*16 .. kt*16+15)
        #pragma unroll
        for (int i = 0; i < 2; i++) {
            int t  = tidx + i * 256;
            int kr = t >> 5;                // 0..15
            int n  = (t & 31) * 4;          // 0..124
            *reinterpret_cast<float4*>(&Bs[kr * 128 + n]) =
                *reinterpret_cast<const float4*>(Wout + (size_t)(kt * 16 + kr) * 128 + n);
        }
        __syncthreads();

        #pragma unroll
        for (int k = 0; k < 16; k++) {
            float a[8], bb[8];
            *reinterpret_cast<float4*>(&a[0]) =
                *reinterpret_cast<const float4*>(&As[k * 132 + ty * 8]);
            *reinterpret_cast<float4*>(&a[4]) =
                *reinterpret_cast<const float4*>(&As[k * 132 + ty * 8 + 4]);
            *reinterpret_cast<float4*>(&bb[0]) =
                *reinterpret_cast<const float4*>(&Bs[k * 128 + tx * 8]);
            *reinterpret_cast<float4*>(&bb[4]) =
                *reinterpret_cast<const float4*>(&Bs[k * 128 + tx * 8 + 4]);
            #pragma unroll
            for (int i = 0; i < 8; i++)
                #pragma unroll
                for (int j = 0; j < 8; j++)
                    acc[i][j] = fmaf(a[i], bb[j], acc[i][j]);
        }
        __syncthreads();
    }

    float bias[8];
    *reinterpret_cast<float4*>(&bias[0]) = *reinterpret_cast<const float4*>(&bout[tx * 8]);
    *reinterpret_cast<float4*>(&bias[4]) = *reinterpret_cast<const float4*>(&bout[tx * 8 + 4]);

    #pragma unroll
    for (int i = 0; i < 8; i++) {
        int row = r0 + ty * 8 + i;
        float4 o0, o1;
        o0.x = tanhf(acc[i][0] + bias[0]);
        o0.y = tanhf(acc[i][1] + bias[1]);
        o0.z = tanhf(acc[i][2] + bias[2]);
        o0.w = tanhf(acc[i][3] + bias[3]);
        o1.x = tanhf(acc[i][4] + bias[4]);
        o1.y = tanhf(acc[i][5] + bias[5]);
        o1.z = tanhf(acc[i][6] + bias[6]);
        o1.w = tanhf(acc[i][7] + bias[7]);
        *reinterpret_cast<float4*>(&out[(size_t)row * 128 + tx * 8])     = o0;
        *reinterpret_cast<float4*>(&out[(size_t)row * 128 + tx * 8 + 4]) = o1;
    }
}

// ============================================================
extern "C" void kernel_launch(void* const* d_in, const int* in_sizes, int n_in,
                              void* d_out, int out_size)
{
    const float* x    = (const float*)d_in[0];
    // d_in[1] = row_splits (uniform; reference ignores it via reshape)
    const float* Ws   = (const float*)d_in[2];
    const float* bs   = (const float*)d_in[3];
    const float* Wf   = (const float*)d_in[4];
    const float* bf   = (const float*)d_in[5];
    const float* Wout = (const float*)d_in[6];
    const float* bout = (const float*)d_in[7];
    float* out = (float*)d_out;

    k_transform<<<N_ / 4, dim3(64, 4)>>>(x, Ws, bs, Wf, bf);
    k_knn<<<dim3(V_ / QPB, B_), 256>>>();
    k_out<<<N_ / 128, 256>>>(x, Wout, bout, out);
}

// round 7
// speedup vs baseline: 1.0540x; 1.0001x over previous
#include <cuda_runtime.h>
#include <math.h>
#include <math_constants.h>

#define B_   32
#define V_   2048
#define K_   40
#define KP1  41
#define FIN  64
#define D_   4
#define P_   64
#define FILT 128
#define N_   (B_ * V_)
#define QPB  8

// ---- scratch (static device arrays: no allocation allowed) ----
__device__ float g_coords[N_ * 4];                  // 1 MB
__device__ float g_feats[(size_t)N_ * FIN];         // 16 MB
__device__ float g_coll[(size_t)N_ * 2 * P_];       // 32 MB

// ============================================================
// Kernel 1: coords = x@W_s + b_s ; feats = x@W_f + b_f
// block (64,4): 4 rows per block, one output column per thread
// ============================================================
__global__ void __launch_bounds__(256) k_transform(
    const float* __restrict__ x,
    const float* __restrict__ Ws, const float* __restrict__ bs,
    const float* __restrict__ Wf, const float* __restrict__ bf)
{
    __shared__ float xs[4][FIN];
    int row = blockIdx.x * 4 + threadIdx.y;
    int c = threadIdx.x;
    xs[threadIdx.y][c] = x[(size_t)row * FIN + c];
    __syncthreads();

    float acc = 0.f;
    #pragma unroll
    for (int k = 0; k < FIN; k++)
        acc = fmaf(xs[threadIdx.y][k], Wf[k * P_ + c], acc);
    g_feats[(size_t)row * FIN + c] = acc + bf[c];

    if (c < D_) {
        float a2 = 0.f;
        #pragma unroll
        for (int k = 0; k < FIN; k++)
            a2 = fmaf(xs[threadIdx.y][k], Ws[k * D_ + c], a2);
        g_coords[row * 4 + c] = a2 + bs[c];
    }
}

// ============================================================
// Kernel 2: exact KNN (top-41 smallest d2 with lax.top_k tie-break,
// drop global min) + Gaussian-weighted feature max/mean pooling.
// One warp per query. d2 keys kept in registers (64/lane).
// ============================================================
__device__ __forceinline__ unsigned keyof(float d2) {
    unsigned u = __float_as_uint(d2);
    // monotonic float->uint map (handles potential tiny negative d2)
    u ^= (u & 0x80000000u) ? 0xFFFFFFFFu : 0x80000000u;
    return u;
}

__device__ __forceinline__ unsigned long long ullmin_(unsigned long long a, unsigned long long b) {
    return a < b ? a : b;
}

__global__ void __launch_bounds__(256, 2) k_knn()
{
    __shared__ float4 sc[V_];               // 32 KB: batch coords
    __shared__ float  ssq[V_];              // 8 KB : squared norms
    __shared__ int    s_idx[QPB][KP1 + 7];
    __shared__ float  s_w[QPB][KP1 + 7];
    __shared__ int    s_cnt[QPB];

    const int b   = blockIdx.y;
    const int tid = threadIdx.x;
    const float4* cg = reinterpret_cast<const float4*>(g_coords) + (size_t)b * V_;
    for (int t = tid; t < V_; t += 256) {
        float4 c = cg[t];
        sc[t]  = c;
        float s = c.x * c.x;
        s = fmaf(c.y, c.y, s); s = fmaf(c.z, c.z, s); s = fmaf(c.w, c.w, s);
        ssq[t] = s;
    }
    __syncthreads();

    const int w    = tid >> 5;
    const int lane = tid & 31;
    const int q    = blockIdx.x * QPB + w;

    const float4 qc  = sc[q];
    const float  qsq = ssq[q];

    // ---- distance keys (same sq+sq-2*dot form as reference selection) ----
    unsigned key[64];
    #pragma unroll
    for (int j = 0; j < 64; j++) {
        int idx = j * 32 + lane;
        float4 c = sc[idx];
        float dot = qc.x * c.x;
        dot = fmaf(qc.y, c.y, dot);
        dot = fmaf(qc.z, c.z, dot);
        dot = fmaf(qc.w, c.w, dot);
        float d2 = qsq + ssq[idx] - 2.f * dot;
        key[j] = keyof(d2);
    }

    // ---- per-lane two smallest -> tight binary-search bounds ----
    unsigned m1 = 0xFFFFFFFFu, m2 = 0xFFFFFFFFu;
    #pragma unroll
    for (int j = 0; j < 64; j++) {
        unsigned u = key[j];
        unsigned nm1 = min(m1, u);
        unsigned nm2 = min(m2, max(m1, u));
        m1 = nm1; m2 = nm2;
    }
    unsigned lo = m1, hi = m2;
    #pragma unroll
    for (int o = 16; o; o >>= 1) {
        lo = min(lo, __shfl_xor_sync(0xffffffffu, lo, o));
        hi = max(hi, __shfl_xor_sync(0xffffffffu, hi, o));
    }
    // invariant: cnt(<=lo-1) < 41  (lo = global min),  cnt(<=hi) >= 64 >= 41

    // ---- binary search smallest T with cnt(<=T) >= 41 ----
    unsigned T = 0;
    bool found = false;
    while (lo < hi) {
        unsigned mid = lo + ((hi - lo) >> 1);
        int c = 0;
        #pragma unroll
        for (int j = 0; j < 64; j++) c += (key[j] <= mid) ? 1 : 0;
        #pragma unroll
        for (int o = 16; o; o >>= 1) c += __shfl_xor_sync(0xffffffffu, c, o);
        if (c == KP1) {   // exact: T = max selected key
            unsigned mx = 0;
            #pragma unroll
            for (int j = 0; j < 64; j++) if (key[j] <= mid) mx = max(mx, key[j]);
            #pragma unroll
            for (int o = 16; o; o >>= 1) mx = max(mx, __shfl_xor_sync(0xffffffffu, mx, o));
            T = mx; found = true; break;
        }
        if (c > KP1) hi = mid; else lo = mid + 1;
    }
    if (!found) T = lo;

    // ---- selection flags: all key<T, plus smallest-index elements with key==T ----
    int c_less = 0;
    #pragma unroll
    for (int j = 0; j < 64; j++) c_less += (key[j] < T) ? 1 : 0;
    #pragma unroll
    for (int o = 16; o; o >>= 1) c_less += __shfl_xor_sync(0xffffffffu, c_less, o);
    const int take_eq = KP1 - c_less;

    unsigned long long selmask = 0ull;
    unsigned long long mymin = 0xFFFFFFFFFFFFFFFFull;
    int running = 0;
    const unsigned lanemask_lt = (1u << lane) - 1u;
    #pragma unroll
    for (int j = 0; j < 64; j++) {
        bool eq = (key[j] == T);
        unsigned bal = __ballot_sync(0xffffffffu, eq);
        bool sel = (key[j] < T);
        if (eq) {
            int rank = running + __popc(bal & lanemask_lt);
            sel = sel || (rank < take_eq);
        }
        running += __popc(bal);
        if (sel) {
            selmask |= (1ull << j);
            unsigned long long ck =
                ((unsigned long long)key[j] << 32) | (unsigned)(j * 32 + lane);
            mymin = ullmin_(mymin, ck);
        }
    }
    #pragma unroll
    for (int o = 16; o; o >>= 1)
        mymin = ullmin_(mymin, __shfl_xor_sync(0xffffffffu, mymin, o));
    const int dropidx = (int)(unsigned)(mymin & 0xffffffffull);  // min (key,idx): dropped

    // ---- build neighbor list (order irrelevant for max/mean) ----
    if (lane == 0) s_cnt[w] = 0;
    __syncwarp();
    unsigned long long m = selmask;
    while (m) {
        int j = __ffsll((long long)m) - 1;
        m &= m - 1;
        int idx = j * 32 + lane;
        if (idx != dropidx) {
            int p = atomicAdd(&s_cnt[w], 1);
            float4 c = sc[idx];
            float dx = qc.x - c.x, dy = qc.y - c.y, dz = qc.z - c.z, dw = qc.w - c.w;
            float dist = dx * dx;
            dist = fmaf(dy, dy, dist);
            dist = fmaf(dz, dz, dist);
            dist = fmaf(dw, dw, dist);
            s_idx[w][p] = idx;
            s_w[w][p]   = expf(-fabsf(dist * 10.f));  // reference weight form
        }
    }
    __syncwarp();
    const int cnt = s_cnt[w];   // == 40 by construction

    // ---- weighted max / mean pooling over neighbors ----
    const float* fb = g_feats + (size_t)b * V_ * FIN;
    float mx0 = -CUDART_INF_F, mx1 = -CUDART_INF_F, sm0 = 0.f, sm1 = 0.f;
    for (int n = 0; n < cnt; n++) {
        int   idx = s_idx[w][n];
        float wt  = s_w[w][n];
        float f0 = fb[(size_t)idx * FIN + lane];
        float f1 = fb[(size_t)idx * FIN + 32 + lane];
        float v0 = f0 * wt, v1 = f1 * wt;
        mx0 = fmaxf(mx0, v0); mx1 = fmaxf(mx1, v1);
        sm0 += v0;            sm1 += v1;
    }
    const int grow = b * V_ + q;
    float* o = g_coll + (size_t)grow * (2 * P_);
    o[lane]       = mx0;
    o[32 + lane]  = mx1;
    o[64 + lane]  = sm0 * (1.f / (float)K_);
    o[96 + lane]  = sm1 * (1.f / (float)K_);
}

// ============================================================
// Kernel 3: out = tanh([x | collected] @ W_out + b_out)
// 128x128 block tile, 8x8 per thread, BK=16, K=192
// ============================================================
__global__ void __launch_bounds__(256) k_out(
    const float* __restrict__ x,
    const float* __restrict__ Wout, const float* __restrict__ bout,
    float* __restrict__ out)
{
    __shared__ float As[16 * 132];   // [k][row], padded stride
    __shared__ float Bs[16 * 128];   // [k][n]

    const int tidx = threadIdx.x;
    const int tx = tidx & 15, ty = tidx >> 4;
    const int r0 = blockIdx.x * 128;

    float acc[8][8];
    #pragma unroll
    for (int i = 0; i < 8; i++)
        #pragma unroll
        for (int j = 0; j < 8; j++) acc[i][j] = 0.f;

    for (int kt = 0; kt < 12; kt++) {
        // load A tile (U = [x | collected])
        #pragma unroll
        for (int i = 0; i < 2; i++) {
            int t   = tidx + i * 256;       // 0..511
            int row = t >> 2;               // 0..127
            int kq  = (t & 3) * 4;          // 0,4,8,12
            int gk  = kt * 16 + kq;
            const float* src = (gk < FIN)
                ? (x      + (size_t)(r0 + row) * FIN  + gk)
                : (g_coll + (size_t)(r0 + row) * 128 + (gk - FIN));
            float4 v = *reinterpret_cast<const float4*>(src);
            As[(kq + 0) * 132 + row] = v.x;
            As[(kq + 1) * 132 + row] = v.y;
            As[(kq + 2) * 132 + row] = v.z;
            As[(kq + 3) * 132 + row] = v.w;
        }
        // load B tile (W_out rows kt*16 .. kt*16+15)
        #pragma unroll
        for (int i = 0; i < 2; i++) {
            int t  = tidx + i * 256;
            int kr = t >> 5;                // 0..15
            int n  = (t & 31) * 4;          // 0..124
            *reinterpret_cast<float4*>(&Bs[kr * 128 + n]) =
                *reinterpret_cast<const float4*>(Wout + (size_t)(kt * 16 + kr) * 128 + n);
        }
        __syncthreads();

        #pragma unroll
        for (int k = 0; k < 16; k++) {
            float a[8], bb[8];
            *reinterpret_cast<float4*>(&a[0]) =
                *reinterpret_cast<const float4*>(&As[k * 132 + ty * 8]);
            *reinterpret_cast<float4*>(&a[4]) =
                *reinterpret_cast<const float4*>(&As[k * 132 + ty * 8 + 4]);
            *reinterpret_cast<float4*>(&bb[0]) =
                *reinterpret_cast<const float4*>(&Bs[k * 128 + tx * 8]);
            *reinterpret_cast<float4*>(&bb[4]) =
                *reinterpret_cast<const float4*>(&Bs[k * 128 + tx * 8 + 4]);
            #pragma unroll
            for (int i = 0; i < 8; i++)
                #pragma unroll
                for (int j = 0; j < 8; j++)
                    acc[i][j] = fmaf(a[i], bb[j], acc[i][j]);
        }
        __syncthreads();
    }

    float bias[8];
    *reinterpret_cast<float4*>(&bias[0]) = *reinterpret_cast<const float4*>(&bout[tx * 8]);
    *reinterpret_cast<float4*>(&bias[4]) = *reinterpret_cast<const float4*>(&bout[tx * 8 + 4]);

    #pragma unroll
    for (int i = 0; i < 8; i++) {
        int row = r0 + ty * 8 + i;
        float4 o0, o1;
        o0.x = tanhf(acc[i][0] + bias[0]);
        o0.y = tanhf(acc[i][1] + bias[1]);
        o0.z = tanhf(acc[i][2] + bias[2]);
        o0.w = tanhf(acc[i][3] + bias[3]);
        o1.x = tanhf(acc[i][4] + bias[4]);
        o1.y = tanhf(acc[i][5] + bias[5]);
        o1.z = tanhf(acc[i][6] + bias[6]);
        o1.w = tanhf(acc[i][7] + bias[7]);
        *reinterpret_cast<float4*>(&out[(size_t)row * 128 + tx * 8])     = o0;
        *reinterpret_cast<float4*>(&out[(size_t)row * 128 + tx * 8 + 4]) = o1;
    }
}

// ============================================================
extern "C" void kernel_launch(void* const* d_in, const int* in_sizes, int n_in,
                              void* d_out, int out_size)
{
    const float* x    = (const float*)d_in[0];
    // d_in[1] = row_splits (uniform; reference ignores it via reshape)
    const float* Ws   = (const float*)d_in[2];
    const float* bs   = (const float*)d_in[3];
    const float* Wf   = (const float*)d_in[4];
    const float* bf   = (const float*)d_in[5];
    const float* Wout = (const float*)d_in[6];
    const float* bout = (const float*)d_in[7];
    float* out = (float*)d_out;

    k_transform<<<N_ / 4, dim3(64, 4)>>>(x, Ws, bs, Wf, bf);
    k_knn<<<dim3(V_ / QPB, B_), 256>>>();
    k_out<<<N_ / 128, 256>>>(x, Wout, bout, out);
}

// round 8
// speedup vs baseline: 1.2550x; 1.1908x over previous
#include <cuda_runtime.h>
#include <math.h>
#include <math_constants.h>

#define B_   32
#define V_   2048
#define K_   40
#define KP1  41
#define FIN  64
#define D_   4
#define P_   64
#define FILT 128
#define N_   (B_ * V_)
#define QPB  8
#define FULL 0xffffffffu

// ---- scratch (static device arrays: no allocation allowed) ----
__device__ float g_coords[N_ * 4];                  // 1 MB
__device__ float g_feats[(size_t)N_ * FIN];         // 16 MB
__device__ float g_coll[(size_t)N_ * 2 * P_];       // 32 MB

// ============================================================
// Kernel 1: coords = x@W_s + b_s ; feats = x@W_f + b_f
// Register-tiled: 64-row tile, Wf + transposed x tile in smem,
// 4x4 outputs per thread (16x16 thread grid).
// ============================================================
__global__ void __launch_bounds__(256) k_transform(
    const float* __restrict__ x,
    const float* __restrict__ Ws, const float* __restrict__ bs,
    const float* __restrict__ Wf, const float* __restrict__ bf)
{
    __shared__ float xsT[64 * 65];   // [k][row], stride 65 (conflict-free)
    __shared__ float wfs[64 * 64];   // [k][c]
    __shared__ float wss[64 * 4];    // [k][c]

    const int tid = threadIdx.x;
    const int r0 = blockIdx.x * 64;

    // stage Wf (16KB) and Ws (1KB)
    #pragma unroll
    for (int i = 0; i < 4; i++) {
        int f = tid + i * 256;
        reinterpret_cast<float4*>(wfs)[f] =
            reinterpret_cast<const float4*>(Wf)[f];
    }
    wss[tid] = Ws[tid];

    // stage x tile transposed: xsT[k][row]
    #pragma unroll
    for (int i = 0; i < 4; i++) {
        int f   = tid + i * 256;        // float4 id 0..1023
        int row = f >> 4;               // 0..63
        int kq  = (f & 15) * 4;         // 0..60
        float4 v = *reinterpret_cast<const float4*>(
            x + (size_t)(r0 + row) * FIN + kq);
        xsT[(kq + 0) * 65 + row] = v.x;
        xsT[(kq + 1) * 65 + row] = v.y;
        xsT[(kq + 2) * 65 + row] = v.z;
        xsT[(kq + 3) * 65 + row] = v.w;
    }
    __syncthreads();

    const int tx = tid & 15, ty = tid >> 4;   // col group, row group
    float acc[4][4];
    #pragma unroll
    for (int i = 0; i < 4; i++)
        #pragma unroll
        for (int j = 0; j < 4; j++) acc[i][j] = 0.f;

    #pragma unroll 16
    for (int k = 0; k < 64; k++) {
        float a0 = xsT[k * 65 + ty * 4 + 0];
        float a1 = xsT[k * 65 + ty * 4 + 1];
        float a2 = xsT[k * 65 + ty * 4 + 2];
        float a3 = xsT[k * 65 + ty * 4 + 3];
        float4 b = *reinterpret_cast<const float4*>(&wfs[k * 64 + tx * 4]);
        acc[0][0] = fmaf(a0, b.x, acc[0][0]); acc[0][1] = fmaf(a0, b.y, acc[0][1]);
        acc[0][2] = fmaf(a0, b.z, acc[0][2]); acc[0][3] = fmaf(a0, b.w, acc[0][3]);
        acc[1][0] = fmaf(a1, b.x, acc[1][0]); acc[1][1] = fmaf(a1, b.y, acc[1][1]);
        acc[1][2] = fmaf(a1, b.z, acc[1][2]); acc[1][3] = fmaf(a1, b.w, acc[1][3]);
        acc[2][0] = fmaf(a2, b.x, acc[2][0]); acc[2][1] = fmaf(a2, b.y, acc[2][1]);
        acc[2][2] = fmaf(a2, b.z, acc[2][2]); acc[2][3] = fmaf(a2, b.w, acc[2][3]);
        acc[3][0] = fmaf(a3, b.x, acc[3][0]); acc[3][1] = fmaf(a3, b.y, acc[3][1]);
        acc[3][2] = fmaf(a3, b.z, acc[3][2]); acc[3][3] = fmaf(a3, b.w, acc[3][3]);
    }

    float4 bfv = *reinterpret_cast<const float4*>(bf + tx * 4);
    #pragma unroll
    for (int i = 0; i < 4; i++) {
        int row = r0 + ty * 4 + i;
        float4 o;
        o.x = acc[i][0] + bfv.x; o.y = acc[i][1] + bfv.y;
        o.z = acc[i][2] + bfv.z; o.w = acc[i][3] + bfv.w;
        *reinterpret_cast<float4*>(g_feats + (size_t)row * FIN + tx * 4) = o;
    }

    // coords: one output per thread
    {
        int crow = tid >> 2, cc = tid & 3;
        float a2 = 0.f;
        #pragma unroll 16
        for (int k = 0; k < 64; k++)
            a2 = fmaf(xsT[k * 65 + crow], wss[k * 4 + cc], a2);
        g_coords[(r0 + crow) * 4 + cc] = a2 + bs[cc];
    }
}

// ============================================================
// Kernel 2: exact KNN + Gaussian-weighted feature max/mean pooling.
// One warp per query. Sampled-pivot bracket + REDUX reductions.
// ============================================================
__device__ __forceinline__ unsigned keyof(float d2) {
    unsigned u = __float_as_uint(d2);
    u ^= (u & 0x80000000u) ? 0xFFFFFFFFu : 0x80000000u;
    return u;
}

__device__ __forceinline__ unsigned long long ullmin_(unsigned long long a, unsigned long long b) {
    return a < b ? a : b;
}

__global__ void __launch_bounds__(256, 2) k_knn()
{
    __shared__ float4 sc[V_];               // 32 KB: batch coords
    __shared__ float  ssq[V_];              // 8 KB : squared norms
    __shared__ int    s_idx[QPB][KP1 + 7];
    __shared__ float  s_w[QPB][KP1 + 7];
    __shared__ int    s_cnt[QPB];

    const int b   = blockIdx.y;
    const int tid = threadIdx.x;
    const float4* cg = reinterpret_cast<const float4*>(g_coords) + (size_t)b * V_;
    for (int t = tid; t < V_; t += 256) {
        float4 c = cg[t];
        sc[t]  = c;
        float s = c.x * c.x;
        s = fmaf(c.y, c.y, s); s = fmaf(c.z, c.z, s); s = fmaf(c.w, c.w, s);
        ssq[t] = s;
    }
    __syncthreads();

    const int w    = tid >> 5;
    const int lane = tid & 31;
    const int q    = blockIdx.x * QPB + w;

    const float4 qc  = sc[q];
    const float  qsq = ssq[q];

    // ---- distance keys (same sq+sq-2*dot form as reference selection) ----
    unsigned key[64];
    #pragma unroll
    for (int j = 0; j < 64; j++) {
        int idx = j * 32 + lane;
        float4 c = sc[idx];
        float dot = qc.x * c.x;
        dot = fmaf(qc.y, c.y, dot);
        dot = fmaf(qc.z, c.z, dot);
        dot = fmaf(qc.w, c.w, dot);
        float d2 = qsq + ssq[idx] - 2.f * dot;
        key[j] = keyof(d2);
    }

    // ---- per-lane two smallest ----
    unsigned m1 = 0xFFFFFFFFu, m2 = 0xFFFFFFFFu;
    #pragma unroll
    for (int j = 0; j < 64; j++) {
        unsigned u = key[j];
        unsigned nm1 = min(m1, u);
        unsigned nm2 = min(m2, max(m1, u));
        m1 = nm1; m2 = nm2;
    }
    const unsigned hi0 = __reduce_max_sync(FULL, m2);   // cnt(<=hi0) >= 64

    // ---- bitonic sort the 32 lane-minima (ascending by lane) ----
    unsigned sv = m1;
    #pragma unroll
    for (int sz = 2; sz <= 32; sz <<= 1) {
        #pragma unroll
        for (int st = sz >> 1; st > 0; st >>= 1) {
            unsigned o = __shfl_xor_sync(FULL, sv, st);
            bool up    = ((lane & sz) == 0);
            bool lower = ((lane & st) == 0);
            unsigned mn = min(sv, o), mx = max(sv, o);
            sv = (lower == up) ? mn : mx;
        }
    }

    // ---- bracket via sampled pivots (counts are measured -> always exact) ----
    int ilo = -1, ihi = 32;
    while (ihi - ilo > 1) {
        int im = (ilo + ihi) >> 1;
        unsigned pv = __shfl_sync(FULL, sv, im);
        int c = 0;
        #pragma unroll
        for (int j = 0; j < 64; j++) c += (key[j] <= pv) ? 1 : 0;
        c = __reduce_add_sync(FULL, c);
        if (c >= KP1) ihi = im; else ilo = im;
    }
    unsigned lo = (ilo >= 0) ? (__shfl_sync(FULL, sv, ilo) + 1u) : 0u;
    unsigned hi = (ihi <= 31) ? __shfl_sync(FULL, sv, ihi) : hi0;

    // ---- value binary search: smallest T with cnt(<=T) >= 41 ----
    unsigned T = 0;
    int cT = 0;
    bool exact = false;
    while (lo < hi) {
        unsigned mid = lo + ((hi - lo) >> 1);
        int c = 0;
        #pragma unroll
        for (int j = 0; j < 64; j++) c += (key[j] <= mid) ? 1 : 0;
        c = __reduce_add_sync(FULL, c);
        if (c == KP1) {   // exact hit: T = max selected key
            unsigned mx = 0;
            #pragma unroll
            for (int j = 0; j < 64; j++) if (key[j] <= mid) mx = max(mx, key[j]);
            T = __reduce_max_sync(FULL, mx);
            cT = KP1; exact = true; break;
        }
        if (c > KP1) hi = mid; else lo = mid + 1;
    }
    if (!exact) {
        T = lo;
        int c = 0;
        #pragma unroll
        for (int j = 0; j < 64; j++) c += (key[j] <= T) ? 1 : 0;
        cT = __reduce_add_sync(FULL, c);
    }

    // ---- selection mask + dropped (min composite) ----
    unsigned long long selmask = 0ull;
    unsigned long long mymin = 0xFFFFFFFFFFFFFFFFull;

    if (cT == KP1) {
        // fast path: no boundary ties
        #pragma unroll
        for (int j = 0; j < 64; j++) {
            if (key[j] <= T) {
                selmask |= (1ull << j);
                unsigned long long ck =
                    ((unsigned long long)key[j] << 32) | (unsigned)(j * 32 + lane);
                mymin = ullmin_(mymin, ck);
            }
        }
    } else {
        // tie path: rank equal-keys by index (lax.top_k stable order)
        int c_less = 0;
        #pragma unroll
        for (int j = 0; j < 64; j++) c_less += (key[j] < T) ? 1 : 0;
        c_less = __reduce_add_sync(FULL, c_less);
        const int take_eq = KP1 - c_less;

        int running = 0;
        const unsigned lanemask_lt = (1u << lane) - 1u;
        #pragma unroll
        for (int j = 0; j < 64; j++) {
            bool eq = (key[j] == T);
            unsigned bal = __ballot_sync(FULL, eq);
            bool sel = (key[j] < T);
            if (eq) {
                int rank = running + __popc(bal & lanemask_lt);
                sel = sel || (rank < take_eq);
            }
            running += __popc(bal);
            if (sel) {
                selmask |= (1ull << j);
                unsigned long long ck =
                    ((unsigned long long)key[j] << 32) | (unsigned)(j * 32 + lane);
                mymin = ullmin_(mymin, ck);
            }
        }
    }
    #pragma unroll
    for (int o = 16; o; o >>= 1)
        mymin = ullmin_(mymin, __shfl_xor_sync(FULL, mymin, o));
    const int dropidx = (int)(unsigned)(mymin & 0xffffffffull);

    // ---- build neighbor list (order irrelevant for max/mean) ----
    if (lane == 0) s_cnt[w] = 0;
    __syncwarp();
    unsigned long long m = selmask;
    while (m) {
        int j = __ffsll((long long)m) - 1;
        m &= m - 1;
        int idx = j * 32 + lane;
        if (idx != dropidx) {
            int p = atomicAdd(&s_cnt[w], 1);
            float4 c = sc[idx];
            float dx = qc.x - c.x, dy = qc.y - c.y, dz = qc.z - c.z, dw = qc.w - c.w;
            float dist = dx * dx;
            dist = fmaf(dy, dy, dist);
            dist = fmaf(dz, dz, dist);
            dist = fmaf(dw, dw, dist);
            s_idx[w][p] = idx;
            s_w[w][p]   = expf(-fabsf(dist * 10.f));
        }
    }
    __syncwarp();
    const int cnt = s_cnt[w];   // == 40 by construction

    // ---- weighted max / mean pooling over neighbors ----
    const float* fb = g_feats + (size_t)b * V_ * FIN;
    float mx0 = -CUDART_INF_F, mx1 = -CUDART_INF_F, sm0 = 0.f, sm1 = 0.f;
    #pragma unroll 4
    for (int n = 0; n < cnt; n++) {
        int   idx = s_idx[w][n];
        float wt  = s_w[w][n];
        float f0 = fb[(size_t)idx * FIN + lane];
        float f1 = fb[(size_t)idx * FIN + 32 + lane];
        float v0 = f0 * wt, v1 = f1 * wt;
        mx0 = fmaxf(mx0, v0); mx1 = fmaxf(mx1, v1);
        sm0 += v0;            sm1 += v1;
    }
    const int grow = b * V_ + q;
    float* o = g_coll + (size_t)grow * (2 * P_);
    o[lane]       = mx0;
    o[32 + lane]  = mx1;
    o[64 + lane]  = sm0 * (1.f / (float)K_);
    o[96 + lane]  = sm1 * (1.f / (float)K_);
}

// ============================================================
// Kernel 3: out = tanh([x | collected] @ W_out + b_out)
// 128x128 block tile, 8x8 per thread, BK=16, K=192
// ============================================================
__global__ void __launch_bounds__(256) k_out(
    const float* __restrict__ x,
    const float* __restrict__ Wout, const float* __restrict__ bout,
    float* __restrict__ out)
{
    __shared__ float As[16 * 132];   // [k][row], padded stride
    __shared__ float Bs[16 * 128];   // [k][n]

    const int tidx = threadIdx.x;
    const int tx = tidx & 15, ty = tidx >> 4;
    const int r0 = blockIdx.x * 128;

    float acc[8][8];
    #pragma unroll
    for (int i = 0; i < 8; i++)
        #pragma unroll
        for (int j = 0; j < 8; j++) acc[i][j] = 0.f;

    for (int kt = 0; kt < 12; kt++) {
        #pragma unroll
        for (int i = 0; i < 2; i++) {
            int t   = tidx + i * 256;       // 0..511
            int row = t >> 2;               // 0..127
            int kq  = (t & 3) * 4;          // 0,4,8,12
            int gk  = kt * 16 + kq;
            const float* src = (gk < FIN)
                ? (x      + (size_t)(r0 + row) * FIN  + gk)
                : (g_coll + (size_t)(r0 + row) * 128 + (gk - FIN));
            float4 v = *reinterpret_cast<const float4*>(src);
            As[(kq + 0) * 132 + row] = v.x;
            As[(kq + 1) * 132 + row] = v.y;
            As[(kq + 2) * 132 + row] = v.z;
            As[(kq + 3) * 132 + row] = v.w;
        }
        #pragma unroll
        for (int i = 0; i < 2; i++) {
            int t  = tidx + i * 256;
            int kr = t >> 5;                // 0..15
            int n  = (t & 31) * 4;          // 0..124
            *reinterpret_cast<float4*>(&Bs[kr * 128 + n]) =
                *reinterpret_cast<const float4*>(Wout + (size_t)(kt * 16 + kr) * 128 + n);
        }
        __syncthreads();

        #pragma unroll
        for (int k = 0; k < 16; k++) {
            float a[8], bb[8];
            *reinterpret_cast<float4*>(&a[0]) =
                *reinterpret_cast<const float4*>(&As[k * 132 + ty * 8]);
            *reinterpret_cast<float4*>(&a[4]) =
                *reinterpret_cast<const float4*>(&As[k * 132 + ty * 8 + 4]);
            *reinterpret_cast<float4*>(&bb[0]) =
                *reinterpret_cast<const float4*>(&Bs[k * 128 + tx * 8]);
            *reinterpret_cast<float4*>(&bb[4]) =
                *reinterpret_cast<const float4*>(&Bs[k * 128 + tx * 8 + 4]);
            #pragma unroll
            for (int i = 0; i < 8; i++)
                #pragma unroll
                for (int j = 0; j < 8; j++)
                    acc[i][j] = fmaf(a[i], bb[j], acc[i][j]);
        }
        __syncthreads();
    }

    float bias[8];
    *reinterpret_cast<float4*>(&bias[0]) = *reinterpret_cast<const float4*>(&bout[tx * 8]);
    *reinterpret_cast<float4*>(&bias[4]) = *reinterpret_cast<const float4*>(&bout[tx * 8 + 4]);

    #pragma unroll
    for (int i = 0; i < 8; i++) {
        int row = r0 + ty * 8 + i;
        float4 o0, o1;
        o0.x = tanhf(acc[i][0] + bias[0]);
        o0.y = tanhf(acc[i][1] + bias[1]);
        o0.z = tanhf(acc[i][2] + bias[2]);
        o0.w = tanhf(acc[i][3] + bias[3]);
        o1.x = tanhf(acc[i][4] + bias[4]);
        o1.y = tanhf(acc[i][5] + bias[5]);
        o1.z = tanhf(acc[i][6] + bias[6]);
        o1.w = tanhf(acc[i][7] + bias[7]);
        *reinterpret_cast<float4*>(&out[(size_t)row * 128 + tx * 8])     = o0;
        *reinterpret_cast<float4*>(&out[(size_t)row * 128 + tx * 8 + 4]) = o1;
    }
}

// ============================================================
extern "C" void kernel_launch(void* const* d_in, const int* in_sizes, int n_in,
                              void* d_out, int out_size)
{
    const float* x    = (const float*)d_in[0];
    // d_in[1] = row_splits (uniform; reference ignores it via reshape)
    const float* Ws   = (const float*)d_in[2];
    const float* bs   = (const float*)d_in[3];
    const float* Wf   = (const float*)d_in[4];
    const float* bf   = (const float*)d_in[5];
    const float* Wout = (const float*)d_in[6];
    const float* bout = (const float*)d_in[7];
    float* out = (float*)d_out;

    k_transform<<<N_ / 64, 256>>>(x, Ws, bs, Wf, bf);
    k_knn<<<dim3(V_ / QPB, B_), 256>>>();
    k_out<<<N_ / 128, 256>>>(x, Wout, bout, out);
}

// round 9
// speedup vs baseline: 1.4242x; 1.1348x over previous
#include <cuda_runtime.h>
#include <math.h>
#include <math_constants.h>

#define B_   32
#define V_   2048
#define K_   40
#define KP1  41
#define FIN  64
#define D_   4
#define P_   64
#define FILT 128
#define N_   (B_ * V_)
#define QPB  8
#define FULL 0xffffffffu
#define CAND_CAP 256

// ---- scratch (static device arrays: no allocation allowed) ----
__device__ float g_coords[N_ * 4];                  // 1 MB
__device__ float g_feats[(size_t)N_ * FIN];         // 16 MB
__device__ float g_coll[(size_t)N_ * 2 * P_];       // 32 MB

// ============================================================
// Kernel 1: coords = x@W_s + b_s ; feats = x@W_f + b_f
// ============================================================
__global__ void __launch_bounds__(256) k_transform(
    const float* __restrict__ x,
    const float* __restrict__ Ws, const float* __restrict__ bs,
    const float* __restrict__ Wf, const float* __restrict__ bf)
{
    __shared__ float xsT[64 * 65];   // [k][row], stride 65
    __shared__ float wfs[64 * 64];   // [k][c]
    __shared__ float wss[64 * 4];    // [k][c]

    const int tid = threadIdx.x;
    const int r0 = blockIdx.x * 64;

    #pragma unroll
    for (int i = 0; i < 4; i++) {
        int f = tid + i * 256;
        reinterpret_cast<float4*>(wfs)[f] =
            reinterpret_cast<const float4*>(Wf)[f];
    }
    wss[tid] = Ws[tid];

    #pragma unroll
    for (int i = 0; i < 4; i++) {
        int f   = tid + i * 256;
        int row = f >> 4;
        int kq  = (f & 15) * 4;
        float4 v = *reinterpret_cast<const float4*>(
            x + (size_t)(r0 + row) * FIN + kq);
        xsT[(kq + 0) * 65 + row] = v.x;
        xsT[(kq + 1) * 65 + row] = v.y;
        xsT[(kq + 2) * 65 + row] = v.z;
        xsT[(kq + 3) * 65 + row] = v.w;
    }
    __syncthreads();

    const int tx = tid & 15, ty = tid >> 4;
    float acc[4][4];
    #pragma unroll
    for (int i = 0; i < 4; i++)
        #pragma unroll
        for (int j = 0; j < 4; j++) acc[i][j] = 0.f;

    #pragma unroll 16
    for (int k = 0; k < 64; k++) {
        float a0 = xsT[k * 65 + ty * 4 + 0];
        float a1 = xsT[k * 65 + ty * 4 + 1];
        float a2 = xsT[k * 65 + ty * 4 + 2];
        float a3 = xsT[k * 65 + ty * 4 + 3];
        float4 b = *reinterpret_cast<const float4*>(&wfs[k * 64 + tx * 4]);
        acc[0][0] = fmaf(a0, b.x, acc[0][0]); acc[0][1] = fmaf(a0, b.y, acc[0][1]);
        acc[0][2] = fmaf(a0, b.z, acc[0][2]); acc[0][3] = fmaf(a0, b.w, acc[0][3]);
        acc[1][0] = fmaf(a1, b.x, acc[1][0]); acc[1][1] = fmaf(a1, b.y, acc[1][1]);
        acc[1][2] = fmaf(a1, b.z, acc[1][2]); acc[1][3] = fmaf(a1, b.w, acc[1][3]);
        acc[2][0] = fmaf(a2, b.x, acc[2][0]); acc[2][1] = fmaf(a2, b.y, acc[2][1]);
        acc[2][2] = fmaf(a2, b.z, acc[2][2]); acc[2][3] = fmaf(a2, b.w, acc[2][3]);
        acc[3][0] = fmaf(a3, b.x, acc[3][0]); acc[3][1] = fmaf(a3, b.y, acc[3][1]);
        acc[3][2] = fmaf(a3, b.z, acc[3][2]); acc[3][3] = fmaf(a3, b.w, acc[3][3]);
    }

    float4 bfv = *reinterpret_cast<const float4*>(bf + tx * 4);
    #pragma unroll
    for (int i = 0; i < 4; i++) {
        int row = r0 + ty * 4 + i;
        float4 o;
        o.x = acc[i][0] + bfv.x; o.y = acc[i][1] + bfv.y;
        o.z = acc[i][2] + bfv.z; o.w = acc[i][3] + bfv.w;
        *reinterpret_cast<float4*>(g_feats + (size_t)row * FIN + tx * 4) = o;
    }

    {
        int crow = tid >> 2, cc = tid & 3;
        float a2 = 0.f;
        #pragma unroll 16
        for (int k = 0; k < 64; k++)
            a2 = fmaf(xsT[k * 65 + crow], wss[k * 4 + cc], a2);
        g_coords[(r0 + crow) * 4 + cc] = a2 + bs[cc];
    }
}

// ============================================================
// Sorting helpers (warp bitonic networks)
// ============================================================
__device__ __forceinline__ unsigned long long shfl_xor_u64(unsigned long long v, int st) {
    unsigned lo = (unsigned)(v & 0xffffffffull);
    unsigned hi = (unsigned)(v >> 32);
    lo = __shfl_xor_sync(FULL, lo, st);
    hi = __shfl_xor_sync(FULL, hi, st);
    return ((unsigned long long)hi << 32) | (unsigned long long)lo;
}

__device__ __forceinline__ void bstep_u32(unsigned &v, int ebase, int sz, int st, int lane) {
    unsigned o = __shfl_xor_sync(FULL, v, st);
    bool up    = ((ebase & sz) == 0);
    bool lower = ((lane & st) == 0);
    unsigned mn = min(v, o), mx = max(v, o);
    v = (lower == up) ? mn : mx;
}

__device__ __forceinline__ void bstep_u64(unsigned long long &v, int ebase, int sz, int st, int lane) {
    unsigned long long o = shfl_xor_u64(v, st);
    bool up    = ((ebase & sz) == 0);
    bool lower = ((lane & st) == 0);
    unsigned long long mn = v < o ? v : o;
    unsigned long long mx = v < o ? o : v;
    v = (lower == up) ? mn : mx;
}

// ascending sort of 64 u32 (2 regs/lane, element e = r*32+lane)
__device__ __forceinline__ void sort64_u32(unsigned &s0, unsigned &s1, int lane) {
    #pragma unroll
    for (int sz = 2; sz <= 32; sz <<= 1) {
        #pragma unroll
        for (int st = sz >> 1; st >= 1; st >>= 1) {
            bstep_u32(s0, lane, sz, st, lane);
            bstep_u32(s1, 32 + lane, sz, st, lane);
        }
    }
    { unsigned mn = min(s0, s1), mx = max(s0, s1); s0 = mn; s1 = mx; }  // st=32 (asc)
    #pragma unroll
    for (int st = 16; st >= 1; st >>= 1) {
        bstep_u32(s0, lane, 64, st, lane);
        bstep_u32(s1, 32 + lane, 64, st, lane);
    }
}

// ascending sort of 64 u64 (2 regs/lane)
__device__ __forceinline__ void sort64_u64(unsigned long long &c0, unsigned long long &c1, int lane) {
    #pragma unroll
    for (int sz = 2; sz <= 32; sz <<= 1) {
        #pragma unroll
        for (int st = sz >> 1; st >= 1; st >>= 1) {
            bstep_u64(c0, lane, sz, st, lane);
            bstep_u64(c1, 32 + lane, sz, st, lane);
        }
    }
    { unsigned long long mn = c0 < c1 ? c0 : c1, mx = c0 < c1 ? c1 : c0; c0 = mn; c1 = mx; }
    #pragma unroll
    for (int st = 16; st >= 1; st >>= 1) {
        bstep_u64(c0, lane, 64, st, lane);
        bstep_u64(c1, 32 + lane, 64, st, lane);
    }
}

// ascending sort of 128 u64 (4 regs/lane)
__device__ __forceinline__ void sort128_u64(
    unsigned long long &c0, unsigned long long &c1,
    unsigned long long &c2, unsigned long long &c3, int lane)
{
    #pragma unroll
    for (int sz = 2; sz <= 32; sz <<= 1) {
        #pragma unroll
        for (int st = sz >> 1; st >= 1; st >>= 1) {
            bstep_u64(c0, lane,      sz, st, lane);
            bstep_u64(c1, 32 + lane, sz, st, lane);
            bstep_u64(c2, 64 + lane, sz, st, lane);
            bstep_u64(c3, 96 + lane, sz, st, lane);
        }
    }
    // sz = 64, st = 32 (local reg pairs): (c0,c1) asc ; (c2,c3) desc
    { unsigned long long mn = c0 < c1 ? c0 : c1, mx = c0 < c1 ? c1 : c0; c0 = mn; c1 = mx; }
    { unsigned long long mn = c2 < c3 ? c2 : c3, mx = c2 < c3 ? c3 : c2; c2 = mx; c3 = mn; }
    #pragma unroll
    for (int st = 16; st >= 1; st >>= 1) {
        bstep_u64(c0, lane,      64, st, lane);
        bstep_u64(c1, 32 + lane, 64, st, lane);
        bstep_u64(c2, 64 + lane, 64, st, lane);
        bstep_u64(c3, 96 + lane, 64, st, lane);
    }
    // sz = 128, st = 64: (c0,c2), (c1,c3) asc
    { unsigned long long mn = c0 < c2 ? c0 : c2, mx = c0 < c2 ? c2 : c0; c0 = mn; c2 = mx; }
    { unsigned long long mn = c1 < c3 ? c1 : c3, mx = c1 < c3 ? c3 : c1; c1 = mn; c3 = mx; }
    // st = 32: (c0,c1), (c2,c3) asc
    { unsigned long long mn = c0 < c1 ? c0 : c1, mx = c0 < c1 ? c1 : c0; c0 = mn; c1 = mx; }
    { unsigned long long mn = c2 < c3 ? c2 : c3, mx = c2 < c3 ? c3 : c2; c2 = mn; c3 = mx; }
    #pragma unroll
    for (int st = 16; st >= 1; st >>= 1) {
        bstep_u64(c0, lane,      128, st, lane);
        bstep_u64(c1, 32 + lane, 128, st, lane);
        bstep_u64(c2, 64 + lane, 128, st, lane);
        bstep_u64(c3, 96 + lane, 128, st, lane);
    }
}

// ============================================================
// Kernel 2: exact KNN + Gaussian-weighted max/mean pooling.
// One warp per query. Candidate-compaction + composite sort:
// sorted (key,idx) candidates give drop=elem0, neighbors=elem1..40.
// ============================================================
__device__ __forceinline__ unsigned keyof(float d2) {
    unsigned u = __float_as_uint(d2);
    u ^= (u & 0x80000000u) ? 0xFFFFFFFFu : 0x80000000u;
    return u;
}
__device__ __forceinline__ unsigned long long ullmin_(unsigned long long a, unsigned long long b) {
    return a < b ? a : b;
}

__global__ void __launch_bounds__(256, 2) k_knn()
{
    __shared__ float4 sc[V_];                              // 32 KB
    __shared__ float  ssq[V_];                             // 8 KB
    __shared__ unsigned long long cand[QPB][CAND_CAP];     // 16 KB
    __shared__ int    s_idx[QPB][KP1 + 7];
    __shared__ float  s_w[QPB][KP1 + 7];
    __shared__ int    s_cnt[QPB];

    const int b   = blockIdx.y;
    const int tid = threadIdx.x;
    const float4* cg = reinterpret_cast<const float4*>(g_coords) + (size_t)b * V_;
    for (int t = tid; t < V_; t += 256) {
        float4 c = cg[t];
        sc[t]  = c;
        float s = c.x * c.x;
        s = fmaf(c.y, c.y, s); s = fmaf(c.z, c.z, s); s = fmaf(c.w, c.w, s);
        ssq[t] = s;
    }
    __syncthreads();

    const int w    = tid >> 5;
    const int lane = tid & 31;
    const int q    = blockIdx.x * QPB + w;
    const unsigned lanemask_lt = (1u << lane) - 1u;

    const float4 qc  = sc[q];
    const float  qsq = ssq[q];

    // ---- distance keys (sq+sq-2*dot, same as reference top_k input) ----
    unsigned key[64];
    #pragma unroll
    for (int j = 0; j < 64; j++) {
        int idx = j * 32 + lane;
        float4 c = sc[idx];
        float dot = qc.x * c.x;
        dot = fmaf(qc.y, c.y, dot);
        dot = fmaf(qc.z, c.z, dot);
        dot = fmaf(qc.w, c.w, dot);
        float d2 = qsq + ssq[idx] - 2.f * dot;
        key[j] = keyof(d2);
    }

    // ---- per-lane two smallest ----
    unsigned m1 = 0xFFFFFFFFu, m2 = 0xFFFFFFFFu;
    #pragma unroll
    for (int j = 0; j < 64; j++) {
        unsigned u = key[j];
        unsigned nm1 = min(m1, u);
        unsigned nm2 = min(m2, max(m1, u));
        m1 = nm1; m2 = nm2;
    }

    // ---- bound B = 41st smallest of the 64-element min2 union ----
    unsigned s0 = m1, s1 = m2;
    sort64_u32(s0, s1, lane);
    const unsigned B   = __shfl_sync(FULL, s1, 8);   // element 40 (r=1, lane=8)
    const unsigned gmin = __shfl_sync(FULL, s0, 0);  // element 0 (global min key)
    // guarantee: cnt(keys <= B) >= 41, and true threshold T <= B.

    // ---- compact candidates (key <= B) as packed (key<<32 | idx) ----
    int base = 0;
    #pragma unroll
    for (int j = 0; j < 64; j++) {
        bool p = (key[j] <= B);
        unsigned bal = __ballot_sync(FULL, p);
        if (p) {
            int pos = base + __popc(bal & lanemask_lt);
            if (pos < CAND_CAP)
                cand[w][pos] = ((unsigned long long)key[j] << 32) | (unsigned)(j * 32 + lane);
        }
        base += __popc(bal);
    }
    const int nc = base;   // >= 41
    __syncwarp();

    int cnt;
    if (nc <= 128) {
        // ======== FAST PATH: sort candidates, read answer directly ========
        const unsigned long long PADV = 0xFFFFFFFFFFFFFFFFull;
        unsigned long long c0 = (lane      < nc) ? cand[w][lane]      : PADV;
        unsigned long long c1 = (32 + lane < nc) ? cand[w][32 + lane] : PADV;
        if (nc <= 64) {
            sort64_u64(c0, c1, lane);
            __syncwarp();
            cand[w][lane]      = c0;
            cand[w][32 + lane] = c1;
        } else {
            unsigned long long c2 = (64 + lane < nc) ? cand[w][64 + lane] : PADV;
            unsigned long long c3 = (96 + lane < nc) ? cand[w][96 + lane] : PADV;
            sort128_u64(c0, c1, c2, c3, lane);
            __syncwarp();
            cand[w][lane]      = c0;
            cand[w][32 + lane] = c1;
            cand[w][64 + lane] = c2;
            cand[w][96 + lane] = c3;
        }
        __syncwarp();
        // sorted[0] = composite min = dropped (self); neighbors = sorted[1..40]
        {
            int idx = (int)(unsigned)(cand[w][1 + lane] & 0xffffffffull);
            float4 c = sc[idx];
            float dx = qc.x - c.x, dy = qc.y - c.y, dz = qc.z - c.z, dw = qc.w - c.w;
            float dist = dx * dx;
            dist = fmaf(dy, dy, dist);
            dist = fmaf(dz, dz, dist);
            dist = fmaf(dw, dw, dist);
            s_idx[w][lane] = idx;
            s_w[w][lane]   = expf(-fabsf(dist * 10.f));
        }
        if (lane < 8) {
            int idx = (int)(unsigned)(cand[w][33 + lane] & 0xffffffffull);
            float4 c = sc[idx];
            float dx = qc.x - c.x, dy = qc.y - c.y, dz = qc.z - c.z, dw = qc.w - c.w;
            float dist = dx * dx;
            dist = fmaf(dy, dy, dist);
            dist = fmaf(dz, dz, dist);
            dist = fmaf(dw, dw, dist);
            s_idx[w][32 + lane] = idx;
            s_w[w][32 + lane]   = expf(-fabsf(dist * 10.f));
        }
        __syncwarp();
        cnt = K_;
    } else {
        // ======== FALLBACK (degenerate ties): exact binary search ========
        unsigned lo = gmin, hi = B;
        unsigned T = 0;
        int cT = 0;
        bool exact = false;
        while (lo < hi) {
            unsigned mid = lo + ((hi - lo) >> 1);
            int c = 0;
            #pragma unroll
            for (int j = 0; j < 64; j++) c += (key[j] <= mid) ? 1 : 0;
            c = __reduce_add_sync(FULL, c);
            if (c == KP1) {
                unsigned mx = 0;
                #pragma unroll
                for (int j = 0; j < 64; j++) if (key[j] <= mid) mx = max(mx, key[j]);
                T = __reduce_max_sync(FULL, mx);
                cT = KP1; exact = true; break;
            }
            if (c > KP1) hi = mid; else lo = mid + 1;
        }
        if (!exact) {
            T = lo;
            int c = 0;
            #pragma unroll
            for (int j = 0; j < 64; j++) c += (key[j] <= T) ? 1 : 0;
            cT = __reduce_add_sync(FULL, c);
        }

        unsigned long long selmask = 0ull;
        unsigned long long mymin = 0xFFFFFFFFFFFFFFFFull;
        if (cT == KP1) {
            #pragma unroll
            for (int j = 0; j < 64; j++) {
                if (key[j] <= T) {
                    selmask |= (1ull << j);
                    unsigned long long ck =
                        ((unsigned long long)key[j] << 32) | (unsigned)(j * 32 + lane);
                    mymin = ullmin_(mymin, ck);
                }
            }
        } else {
            int c_less = 0;
            #pragma unroll
            for (int j = 0; j < 64; j++) c_less += (key[j] < T) ? 1 : 0;
            c_less = __reduce_add_sync(FULL, c_less);
            const int take_eq = KP1 - c_less;
            int running = 0;
            #pragma unroll
            for (int j = 0; j < 64; j++) {
                bool eq = (key[j] == T);
                unsigned bal = __ballot_sync(FULL, eq);
                bool sel = (key[j] < T);
                if (eq) {
                    int rank = running + __popc(bal & lanemask_lt);
                    sel = sel || (rank < take_eq);
                }
                running += __popc(bal);
                if (sel) {
                    selmask |= (1ull << j);
                    unsigned long long ck =
                        ((unsigned long long)key[j] << 32) | (unsigned)(j * 32 + lane);
                    mymin = ullmin_(mymin, ck);
                }
            }
        }
        #pragma unroll
        for (int o = 16; o; o >>= 1)
            mymin = ullmin_(mymin, __shfl_xor_sync(FULL, mymin, o));
        const int dropidx = (int)(unsigned)(mymin & 0xffffffffull);

        if (lane == 0) s_cnt[w] = 0;
        __syncwarp();
        unsigned long long m = selmask;
        while (m) {
            int j = __ffsll((long long)m) - 1;
            m &= m - 1;
            int idx = j * 32 + lane;
            if (idx != dropidx) {
                int p = atomicAdd(&s_cnt[w], 1);
                float4 c = sc[idx];
                float dx = qc.x - c.x, dy = qc.y - c.y, dz = qc.z - c.z, dw = qc.w - c.w;
                float dist = dx * dx;
                dist = fmaf(dy, dy, dist);
                dist = fmaf(dz, dz, dist);
                dist = fmaf(dw, dw, dist);
                s_idx[w][p] = idx;
                s_w[w][p]   = expf(-fabsf(dist * 10.f));
            }
        }
        __syncwarp();
        cnt = s_cnt[w];
    }

    // ---- weighted max / mean pooling over neighbors ----
    const float* fb = g_feats + (size_t)b * V_ * FIN;
    float mx0 = -CUDART_INF_F, mx1 = -CUDART_INF_F, sm0 = 0.f, sm1 = 0.f;
    #pragma unroll 4
    for (int n = 0; n < cnt; n++) {
        int   idx = s_idx[w][n];
        float wt  = s_w[w][n];
        float f0 = fb[(size_t)idx * FIN + lane];
        float f1 = fb[(size_t)idx * FIN + 32 + lane];
        float v0 = f0 * wt, v1 = f1 * wt;
        mx0 = fmaxf(mx0, v0); mx1 = fmaxf(mx1, v1);
        sm0 += v0;            sm1 += v1;
    }
    const int grow = b * V_ + q;
    float* o = g_coll + (size_t)grow * (2 * P_);
    o[lane]       = mx0;
    o[32 + lane]  = mx1;
    o[64 + lane]  = sm0 * (1.f / (float)K_);
    o[96 + lane]  = sm1 * (1.f / (float)K_);
}

// ============================================================
// Kernel 3: out = tanh([x | collected] @ W_out + b_out)
// ============================================================
__global__ void __launch_bounds__(256) k_out(
    const float* __restrict__ x,
    const float* __restrict__ Wout, const float* __restrict__ bout,
    float* __restrict__ out)
{
    __shared__ float As[16 * 132];
    __shared__ float Bs[16 * 128];

    const int tidx = threadIdx.x;
    const int tx = tidx & 15, ty = tidx >> 4;
    const int r0 = blockIdx.x * 128;

    float acc[8][8];
    #pragma unroll
    for (int i = 0; i < 8; i++)
        #pragma unroll
        for (int j = 0; j < 8; j++) acc[i][j] = 0.f;

    for (int kt = 0; kt < 12; kt++) {
        #pragma unroll
        for (int i = 0; i < 2; i++) {
            int t   = tidx + i * 256;
            int row = t >> 2;
            int kq  = (t & 3) * 4;
            int gk  = kt * 16 + kq;
            const float* src = (gk < FIN)
                ? (x      + (size_t)(r0 + row) * FIN  + gk)
                : (g_coll + (size_t)(r0 + row) * 128 + (gk - FIN));
            float4 v = *reinterpret_cast<const float4*>(src);
            As[(kq + 0) * 132 + row] = v.x;
            As[(kq + 1) * 132 + row] = v.y;
            As[(kq + 2) * 132 + row] = v.z;
            As[(kq + 3) * 132 + row] = v.w;
        }
        #pragma unroll
        for (int i = 0; i < 2; i++) {
            int t  = tidx + i * 256;
            int kr = t >> 5;
            int n  = (t & 31) * 4;
            *reinterpret_cast<float4*>(&Bs[kr * 128 + n]) =
                *reinterpret_cast<const float4*>(Wout + (size_t)(kt * 16 + kr) * 128 + n);
        }
        __syncthreads();

        #pragma unroll
        for (int k = 0; k < 16; k++) {
            float a[8], bb[8];
            *reinterpret_cast<float4*>(&a[0]) =
                *reinterpret_cast<const float4*>(&As[k * 132 + ty * 8]);
            *reinterpret_cast<float4*>(&a[4]) =
                *reinterpret_cast<const float4*>(&As[k * 132 + ty * 8 + 4]);
            *reinterpret_cast<float4*>(&bb[0]) =
                *reinterpret_cast<const float4*>(&Bs[k * 128 + tx * 8]);
            *reinterpret_cast<float4*>(&bb[4]) =
                *reinterpret_cast<const float4*>(&Bs[k * 128 + tx * 8 + 4]);
            #pragma unroll
            for (int i = 0; i < 8; i++)
                #pragma unroll
                for (int j = 0; j < 8; j++)
                    acc[i][j] = fmaf(a[i], bb[j], acc[i][j]);
        }
        __syncthreads();
    }

    float bias[8];
    *reinterpret_cast<float4*>(&bias[0]) = *reinterpret_cast<const float4*>(&bout[tx * 8]);
    *reinterpret_cast<float4*>(&bias[4]) = *reinterpret_cast<const float4*>(&bout[tx * 8 + 4]);

    #pragma unroll
    for (int i = 0; i < 8; i++) {
        int row = r0 + ty * 8 + i;
        float4 o0, o1;
        o0.x = tanhf(acc[i][0] + bias[0]);
        o0.y = tanhf(acc[i][1] + bias[1]);
        o0.z = tanhf(acc[i][2] + bias[2]);
        o0.w = tanhf(acc[i][3] + bias[3]);
        o1.x = tanhf(acc[i][4] + bias[4]);
        o1.y = tanhf(acc[i][5] + bias[5]);
        o1.z = tanhf(acc[i][6] + bias[6]);
        o1.w = tanhf(acc[i][7] + bias[7]);
        *reinterpret_cast<float4*>(&out[(size_t)row * 128 + tx * 8])     = o0;
        *reinterpret_cast<float4*>(&out[(size_t)row * 128 + tx * 8 + 4]) = o1;
    }
}

// ============================================================
extern "C" void kernel_launch(void* const* d_in, const int* in_sizes, int n_in,
                              void* d_out, int out_size)
{
    const float* x    = (const float*)d_in[0];
    const float* Ws   = (const float*)d_in[2];
    const float* bs   = (const float*)d_in[3];
    const float* Wf   = (const float*)d_in[4];
    const float* bf   = (const float*)d_in[5];
    const float* Wout = (const float*)d_in[6];
    const float* bout = (const float*)d_in[7];
    float* out = (float*)d_out;

    k_transform<<<N_ / 64, 256>>>(x, Ws, bs, Wf, bf);
    k_knn<<<dim3(V_ / QPB, B_), 256>>>();
    k_out<<<N_ / 128, 256>>>(x, Wout, bout, out);
}

// round 10
// speedup vs baseline: 1.6449x; 1.1550x over previous
#include <cuda_runtime.h>
#include <math.h>
#include <math_constants.h>

#define B_   32
#define V_   2048
#define K_   40
#define KP1  41
#define FIN  64
#define D_   4
#define P_   64
#define FILT 128
#define N_   (B_ * V_)
#define QPB  8
#define FULL 0xffffffffu

// ---- scratch (static device arrays: no allocation allowed) ----
__device__ float g_coords[N_ * 4];                  // 1 MB
__device__ float g_feats[(size_t)N_ * FIN];         // 16 MB
__device__ float g_coll[(size_t)N_ * 2 * P_];       // 32 MB

// ============================================================
// Kernel 1: coords = x@W_s + b_s ; feats = x@W_f + b_f
// ============================================================
__global__ void __launch_bounds__(256) k_transform(
    const float* __restrict__ x,
    const float* __restrict__ Ws, const float* __restrict__ bs,
    const float* __restrict__ Wf, const float* __restrict__ bf)
{
    __shared__ float xsT[64 * 65];
    __shared__ float wfs[64 * 64];
    __shared__ float wss[64 * 4];

    const int tid = threadIdx.x;
    const int r0 = blockIdx.x * 64;

    #pragma unroll
    for (int i = 0; i < 4; i++) {
        int f = tid + i * 256;
        reinterpret_cast<float4*>(wfs)[f] =
            reinterpret_cast<const float4*>(Wf)[f];
    }
    wss[tid] = Ws[tid];

    #pragma unroll
    for (int i = 0; i < 4; i++) {
        int f   = tid + i * 256;
        int row = f >> 4;
        int kq  = (f & 15) * 4;
        float4 v = *reinterpret_cast<const float4*>(
            x + (size_t)(r0 + row) * FIN + kq);
        xsT[(kq + 0) * 65 + row] = v.x;
        xsT[(kq + 1) * 65 + row] = v.y;
        xsT[(kq + 2) * 65 + row] = v.z;
        xsT[(kq + 3) * 65 + row] = v.w;
    }
    __syncthreads();

    const int tx = tid & 15, ty = tid >> 4;
    float acc[4][4];
    #pragma unroll
    for (int i = 0; i < 4; i++)
        #pragma unroll
        for (int j = 0; j < 4; j++) acc[i][j] = 0.f;

    #pragma unroll 16
    for (int k = 0; k < 64; k++) {
        float a0 = xsT[k * 65 + ty * 4 + 0];
        float a1 = xsT[k * 65 + ty * 4 + 1];
        float a2 = xsT[k * 65 + ty * 4 + 2];
        float a3 = xsT[k * 65 + ty * 4 + 3];
        float4 b = *reinterpret_cast<const float4*>(&wfs[k * 64 + tx * 4]);
        acc[0][0] = fmaf(a0, b.x, acc[0][0]); acc[0][1] = fmaf(a0, b.y, acc[0][1]);
        acc[0][2] = fmaf(a0, b.z, acc[0][2]); acc[0][3] = fmaf(a0, b.w, acc[0][3]);
        acc[1][0] = fmaf(a1, b.x, acc[1][0]); acc[1][1] = fmaf(a1, b.y, acc[1][1]);
        acc[1][2] = fmaf(a1, b.z, acc[1][2]); acc[1][3] = fmaf(a1, b.w, acc[1][3]);
        acc[2][0] = fmaf(a2, b.x, acc[2][0]); acc[2][1] = fmaf(a2, b.y, acc[2][1]);
        acc[2][2] = fmaf(a2, b.z, acc[2][2]); acc[2][3] = fmaf(a2, b.w, acc[2][3]);
        acc[3][0] = fmaf(a3, b.x, acc[3][0]); acc[3][1] = fmaf(a3, b.y, acc[3][1]);
        acc[3][2] = fmaf(a3, b.z, acc[3][2]); acc[3][3] = fmaf(a3, b.w, acc[3][3]);
    }

    float4 bfv = *reinterpret_cast<const float4*>(bf + tx * 4);
    #pragma unroll
    for (int i = 0; i < 4; i++) {
        int row = r0 + ty * 4 + i;
        float4 o;
        o.x = acc[i][0] + bfv.x; o.y = acc[i][1] + bfv.y;
        o.z = acc[i][2] + bfv.z; o.w = acc[i][3] + bfv.w;
        *reinterpret_cast<float4*>(g_feats + (size_t)row * FIN + tx * 4) = o;
    }

    {
        int crow = tid >> 2, cc = tid & 3;
        float a2 = 0.f;
        #pragma unroll 16
        for (int k = 0; k < 64; k++)
            a2 = fmaf(xsT[k * 65 + crow], wss[k * 4 + cc], a2);
        g_coords[(r0 + crow) * 4 + cc] = a2 + bs[cc];
    }
}

// ============================================================
// warp bitonic sort of 64 u32 (2 regs/lane, element e = r*32+lane)
// ============================================================
__device__ __forceinline__ void bstep_u32(unsigned &v, int ebase, int sz, int st, int lane) {
    unsigned o = __shfl_xor_sync(FULL, v, st);
    bool up    = ((ebase & sz) == 0);
    bool lower = ((lane & st) == 0);
    unsigned mn = min(v, o), mx = max(v, o);
    v = (lower == up) ? mn : mx;
}

__device__ __forceinline__ void sort64_u32(unsigned &s0, unsigned &s1, int lane) {
    #pragma unroll
    for (int sz = 2; sz <= 32; sz <<= 1) {
        #pragma unroll
        for (int st = sz >> 1; st >= 1; st >>= 1) {
            bstep_u32(s0, lane, sz, st, lane);
            bstep_u32(s1, 32 + lane, sz, st, lane);
        }
    }
    { unsigned mn = min(s0, s1), mx = max(s0, s1); s0 = mn; s1 = mx; }
    #pragma unroll
    for (int st = 16; st >= 1; st >>= 1) {
        bstep_u32(s0, lane, 64, st, lane);
        bstep_u32(s1, 32 + lane, 64, st, lane);
    }
}

// ============================================================
// Kernel 2: exact KNN + Gaussian-weighted max/mean pooling.
// ============================================================
__device__ __forceinline__ unsigned keyof(float d2) {
    unsigned u = __float_as_uint(d2);
    u ^= (u & 0x80000000u) ? 0xFFFFFFFFu : 0x80000000u;
    return u;
}
__device__ __forceinline__ unsigned long long ullmin_(unsigned long long a, unsigned long long b) {
    return a < b ? a : b;
}

__global__ void __launch_bounds__(256, 2) k_knn()
{
    __shared__ float4 sc[V_];                      // 32 KB
    __shared__ float  ssq[V_];                     // 8 KB
    __shared__ unsigned candk[QPB][64];            // 2 KB (candidate keys)
    __shared__ float2 s_iw[QPB][K_];               // 2.5 KB (weight, idx)

    const int b   = blockIdx.y;
    const int tid = threadIdx.x;
    const float4* cg = reinterpret_cast<const float4*>(g_coords) + (size_t)b * V_;
    for (int t = tid; t < V_; t += 256) {
        float4 c = cg[t];
        sc[t]  = c;
        float s = c.x * c.x;
        s = fmaf(c.y, c.y, s); s = fmaf(c.z, c.z, s); s = fmaf(c.w, c.w, s);
        ssq[t] = s;
    }
    __syncthreads();

    const int w    = tid >> 5;
    const int lane = tid & 31;
    const int q    = blockIdx.x * QPB + w;
    const unsigned lanemask_lt = (1u << lane) - 1u;

    const float4 qc  = sc[q];
    const float  qsq = ssq[q];

    // ---- distance keys + fused per-lane two smallest ----
    unsigned key[64];
    unsigned m1 = 0xFFFFFFFFu, m2 = 0xFFFFFFFFu;
    #pragma unroll
    for (int j = 0; j < 64; j++) {
        int idx = j * 32 + lane;
        float4 c = sc[idx];
        float dot = qc.x * c.x;
        dot = fmaf(qc.y, c.y, dot);
        dot = fmaf(qc.z, c.z, dot);
        dot = fmaf(qc.w, c.w, dot);
        float d2 = qsq + ssq[idx] - 2.f * dot;
        unsigned u = keyof(d2);
        key[j] = u;
        unsigned nm1 = min(m1, u);
        unsigned nm2 = min(m2, max(m1, u));
        m1 = nm1; m2 = nm2;
    }

    // ---- B = 41st smallest of min2 union (upper bound on threshold) ----
    unsigned s0 = m1, s1 = m2;
    sort64_u32(s0, s1, lane);
    const unsigned B    = __shfl_sync(FULL, s1, 8);   // element 40
    const unsigned gmin = __shfl_sync(FULL, s0, 0);   // element 0

    // ---- candidate membership mask (key <= B), prefix-scan compaction ----
    unsigned long long candmask = 0ull;
    #pragma unroll
    for (int j = 0; j < 64; j++)
        if (key[j] <= B) candmask |= (1ull << j);

    int myCnt = __popcll(candmask);
    int scan = myCnt;
    #pragma unroll
    for (int o = 1; o < 32; o <<= 1) {
        int v = __shfl_up_sync(FULL, scan, o);
        if (lane >= o) scan += v;
    }
    const int nc   = __shfl_sync(FULL, scan, 31);
    int pos = scan - myCnt;

    unsigned long long selmask = 0ull;   // final selected set (41 incl drop)

    if (nc <= 64) {
        // ======== FAST PATH ========
        {
            unsigned long long m = candmask;
            while (m) {
                int j = __ffsll((long long)m) - 1;
                m &= m - 1;
                candk[w][pos++] = key[j];
            }
        }
        __syncwarp();
        unsigned c0 = (lane      < nc) ? candk[w][lane]      : 0xFFFFFFFFu;
        unsigned c1 = (32 + lane < nc) ? candk[w][32 + lane] : 0xFFFFFFFFu;
        sort64_u32(c0, c1, lane);
        const unsigned T  = __shfl_sync(FULL, c1, 8);    // element 40 = 41st key
        const unsigned T1 = __shfl_sync(FULL, c1, 9);    // element 41
        const bool tie = (nc >= 42) && (T1 == T);

        if (!tie) {
            // exactly 41 keys <= T
            #pragma unroll
            for (int j = 0; j < 64; j++)
                if (key[j] <= T) selmask |= (1ull << j);
        } else {
            // boundary tie: rank equal keys by index (lax.top_k stable order)
            int c_less = 0;
            #pragma unroll
            for (int j = 0; j < 64; j++) c_less += (key[j] < T) ? 1 : 0;
            c_less = __reduce_add_sync(FULL, c_less);
            const int take_eq = KP1 - c_less;
            int running = 0;
            #pragma unroll
            for (int j = 0; j < 64; j++) {
                bool eq = (key[j] == T);
                unsigned bal = __ballot_sync(FULL, eq);
                bool sel = (key[j] < T);
                if (eq) {
                    int rank = running + __popc(bal & lanemask_lt);
                    sel = sel || (rank < take_eq);
                }
                running += __popc(bal);
                if (sel) selmask |= (1ull << j);
            }
        }
    } else {
        // ======== FALLBACK (degenerate): exact binary search ========
        unsigned lo = gmin, hi = B;
        unsigned T = 0;
        int cT = 0;
        bool exact = false;
        while (lo < hi) {
            unsigned mid = lo + ((hi - lo) >> 1);
            int c = 0;
            #pragma unroll
            for (int j = 0; j < 64; j++) c += (key[j] <= mid) ? 1 : 0;
            c = __reduce_add_sync(FULL, c);
            if (c == KP1) {
                unsigned mx = 0;
                #pragma unroll
                for (int j = 0; j < 64; j++) if (key[j] <= mid) mx = max(mx, key[j]);
                T = __reduce_max_sync(FULL, mx);
                cT = KP1; exact = true; break;
            }
            if (c > KP1) hi = mid; else lo = mid + 1;
        }
        if (!exact) {
            T = lo;
            int c = 0;
            #pragma unroll
            for (int j = 0; j < 64; j++) c += (key[j] <= T) ? 1 : 0;
            cT = __reduce_add_sync(FULL, c);
        }
        if (cT == KP1) {
            #pragma unroll
            for (int j = 0; j < 64; j++)
                if (key[j] <= T) selmask |= (1ull << j);
        } else {
            int c_less = 0;
            #pragma unroll
            for (int j = 0; j < 64; j++) c_less += (key[j] < T) ? 1 : 0;
            c_less = __reduce_add_sync(FULL, c_less);
            const int take_eq = KP1 - c_less;
            int running = 0;
            #pragma unroll
            for (int j = 0; j < 64; j++) {
                bool eq = (key[j] == T);
                unsigned bal = __ballot_sync(FULL, eq);
                bool sel = (key[j] < T);
                if (eq) {
                    int rank = running + __popc(bal & lanemask_lt);
                    sel = sel || (rank < take_eq);
                }
                running += __popc(bal);
                if (sel) selmask |= (1ull << j);
            }
        }
    }

    // ---- common epilogue: drop = min composite; write (weight, idx) ----
    unsigned long long mymin = 0xFFFFFFFFFFFFFFFFull;
    {
        unsigned long long m = selmask;
        while (m) {
            int j = __ffsll((long long)m) - 1;
            m &= m - 1;
            unsigned long long ck =
                ((unsigned long long)key[j] << 32) | (unsigned)(j * 32 + lane);
            mymin = ullmin_(mymin, ck);
        }
    }
    #pragma unroll
    for (int o = 16; o; o >>= 1)
        mymin = ullmin_(mymin, __shfl_xor_sync(FULL, mymin, o));
    const int dropidx = (int)(unsigned)(mymin & 0xffffffffull);
    if ((dropidx & 31) == lane)
        selmask &= ~(1ull << (dropidx >> 5));

    {
        int cnt = __popcll(selmask);
        int sc2 = cnt;
        #pragma unroll
        for (int o = 1; o < 32; o <<= 1) {
            int v = __shfl_up_sync(FULL, sc2, o);
            if (lane >= o) sc2 += v;
        }
        int p = sc2 - cnt;
        unsigned long long m = selmask;
        while (m) {
            int j = __ffsll((long long)m) - 1;
            m &= m - 1;
            int idx = j * 32 + lane;
            float4 c = sc[idx];
            float dx = qc.x - c.x, dy = qc.y - c.y, dz = qc.z - c.z, dw = qc.w - c.w;
            float dist = dx * dx;
            dist = fmaf(dy, dy, dist);
            dist = fmaf(dz, dz, dist);
            dist = fmaf(dw, dw, dist);
            float2 iw;
            iw.x = expf(-fabsf(dist * 10.f));
            iw.y = __int_as_float(idx);
            if (p < K_) s_iw[w][p] = iw;
            p++;
        }
    }
    __syncwarp();

    // ---- weighted max / mean pooling over the 40 neighbors ----
    const float* fb = g_feats + (size_t)b * V_ * FIN;
    float mx0 = -CUDART_INF_F, mx1 = -CUDART_INF_F, sm0 = 0.f, sm1 = 0.f;
    #pragma unroll 8
    for (int n = 0; n < K_; n++) {
        float2 iw = s_iw[w][n];
        int   idx = __float_as_int(iw.y);
        float wt  = iw.x;
        float f0 = fb[(size_t)idx * FIN + lane];
        float f1 = fb[(size_t)idx * FIN + 32 + lane];
        float v0 = f0 * wt, v1 = f1 * wt;
        mx0 = fmaxf(mx0, v0); mx1 = fmaxf(mx1, v1);
        sm0 += v0;            sm1 += v1;
    }
    const int grow = b * V_ + q;
    float* o = g_coll + (size_t)grow * (2 * P_);
    o[lane]       = mx0;
    o[32 + lane]  = mx1;
    o[64 + lane]  = sm0 * (1.f / (float)K_);
    o[96 + lane]  = sm1 * (1.f / (float)K_);
}

// ============================================================
// Kernel 3: out = tanh([x | collected] @ W_out + b_out)
// ============================================================
__global__ void __launch_bounds__(256) k_out(
    const float* __restrict__ x,
    const float* __restrict__ Wout, const float* __restrict__ bout,
    float* __restrict__ out)
{
    __shared__ float As[16 * 132];
    __shared__ float Bs[16 * 128];

    const int tidx = threadIdx.x;
    const int tx = tidx & 15, ty = tidx >> 4;
    const int r0 = blockIdx.x * 128;

    float acc[8][8];
    #pragma unroll
    for (int i = 0; i < 8; i++)
        #pragma unroll
        for (int j = 0; j < 8; j++) acc[i][j] = 0.f;

    for (int kt = 0; kt < 12; kt++) {
        #pragma unroll
        for (int i = 0; i < 2; i++) {
            int t   = tidx + i * 256;
            int row = t >> 2;
            int kq  = (t & 3) * 4;
            int gk  = kt * 16 + kq;
            const float* src = (gk < FIN)
                ? (x      + (size_t)(r0 + row) * FIN  + gk)
                : (g_coll + (size_t)(r0 + row) * 128 + (gk - FIN));
            float4 v = *reinterpret_cast<const float4*>(src);
            As[(kq + 0) * 132 + row] = v.x;
            As[(kq + 1) * 132 + row] = v.y;
            As[(kq + 2) * 132 + row] = v.z;
            As[(kq + 3) * 132 + row] = v.w;
        }
        #pragma unroll
        for (int i = 0; i < 2; i++) {
            int t  = tidx + i * 256;
            int kr = t >> 5;
            int n  = (t & 31) * 4;
            *reinterpret_cast<float4*>(&Bs[kr * 128 + n]) =
                *reinterpret_cast<const float4*>(Wout + (size_t)(kt * 16 + kr) * 128 + n);
        }
        __syncthreads();

        #pragma unroll
        for (int k = 0; k < 16; k++) {
            float a[8], bb[8];
            *reinterpret_cast<float4*>(&a[0]) =
                *reinterpret_cast<const float4*>(&As[k * 132 + ty * 8]);
            *reinterpret_cast<float4*>(&a[4]) =
                *reinterpret_cast<const float4*>(&As[k * 132 + ty * 8 + 4]);
            *reinterpret_cast<float4*>(&bb[0]) =
                *reinterpret_cast<const float4*>(&Bs[k * 128 + tx * 8]);
            *reinterpret_cast<float4*>(&bb[4]) =
                *reinterpret_cast<const float4*>(&Bs[k * 128 + tx * 8 + 4]);
            #pragma unroll
            for (int i = 0; i < 8; i++)
                #pragma unroll
                for (int j = 0; j < 8; j++)
                    acc[i][j] = fmaf(a[i], bb[j], acc[i][j]);
        }
        __syncthreads();
    }

    float bias[8];
    *reinterpret_cast<float4*>(&bias[0]) = *reinterpret_cast<const float4*>(&bout[tx * 8]);
    *reinterpret_cast<float4*>(&bias[4]) = *reinterpret_cast<const float4*>(&bout[tx * 8 + 4]);

    #pragma unroll
    for (int i = 0; i < 8; i++) {
        int row = r0 + ty * 8 + i;
        float4 o0, o1;
        o0.x = tanhf(acc[i][0] + bias[0]);
        o0.y = tanhf(acc[i][1] + bias[1]);
        o0.z = tanhf(acc[i][2] + bias[2]);
        o0.w = tanhf(acc[i][3] + bias[3]);
        o1.x = tanhf(acc[i][4] + bias[4]);
        o1.y = tanhf(acc[i][5] + bias[5]);
        o1.z = tanhf(acc[i][6] + bias[6]);
        o1.w = tanhf(acc[i][7] + bias[7]);
        *reinterpret_cast<float4*>(&out[(size_t)row * 128 + tx * 8])     = o0;
        *reinterpret_cast<float4*>(&out[(size_t)row * 128 + tx * 8 + 4]) = o1;
    }
}

// ============================================================
extern "C" void kernel_launch(void* const* d_in, const int* in_sizes, int n_in,
                              void* d_out, int out_size)
{
    const float* x    = (const float*)d_in[0];
    const float* Ws   = (const float*)d_in[2];
    const float* bs   = (const float*)d_in[3];
    const float* Wf   = (const float*)d_in[4];
    const float* bf   = (const float*)d_in[5];
    const float* Wout = (const float*)d_in[6];
    const float* bout = (const float*)d_in[7];
    float* out = (float*)d_out;

    k_transform<<<N_ / 64, 256>>>(x, Ws, bs, Wf, bf);
    k_knn<<<dim3(V_ / QPB, B_), 256>>>();
    k_out<<<N_ / 128, 256>>>(x, Wout, bout, out);
}